// round 1
// baseline (speedup 1.0000x reference)
#include <cuda_runtime.h>
#include <cstdint>

// ---------------- problem constants ----------------
#define Bb    8
#define Nn    2048
#define Dd    512
#define HIDc  2048
#define DQK   128
#define GRP   256
#define Gg    8            // Nn / GRP
#define NT    (Bb*Nn)      // 16384 tokens
#define Ee    1024         // HID/2
#define KK    17

// ---------------- scratch (device globals; allocation-free) ----------------
__device__ float g_bufA[(size_t)NT*HIDc];   // h (silu out), later att_v|att_u
__device__ float g_hid [(size_t)NT*HIDc];   // v|u after conv
__device__ float g_ln  [(size_t)NT*1024];   // LN outputs (512- or 1024-wide)
__device__ float g_nx  [(size_t)NT*Dd];     // shifted x; later o_pre (silu out)
__device__ float g_gate[(size_t)NT*Ee];     // gated out
__device__ float g_kv  [(size_t)Bb*Gg*DQK*HIDc]; // lin kv|ku, cumsummed in place
__device__ float g_qk  [(size_t)NT*DQK];    // qk pre-conv
__device__ float g_qk2 [(size_t)NT*DQK];    // qk post-conv
__device__ float g_qs  [(size_t)4*NT*DQK];  // quad_q, lin_q, quad_k, lin_k
__device__ float g_attn[(size_t)Bb*Gg*GRP*GRP];

// ---------------- elementwise kernels ----------------
__global__ void shift_k(const float* __restrict__ x, float* __restrict__ nx) {
    long i = (long)blockIdx.x * blockDim.x + threadIdx.x;
    if (i >= (long)NT*Dd) return;
    int c = (int)(i % Dd);
    long t = i / Dd;
    int n = (int)(t % Nn);
    float v;
    if (c < Dd/2) v = (n == 0) ? 0.f : x[i - Dd];
    else          v = x[i];
    nx[i] = v;
}

__global__ void qsplit_k(const float* __restrict__ qk, const float* __restrict__ gamma,
                         const float* __restrict__ beta, float* __restrict__ qs) {
    long i = (long)blockIdx.x * blockDim.x + threadIdx.x;
    if (i >= (long)NT*DQK) return;
    int d = (int)(i % DQK);
    float v = qk[i];
    #pragma unroll
    for (int s = 0; s < 4; s++)
        qs[(long)s*NT*DQK + i] = v * gamma[s*DQK + d] + beta[s*DQK + d];
}

__global__ void cumsum_k(float* __restrict__ kv) {
    long i = (long)blockIdx.x * blockDim.x + threadIdx.x;       // over Bb*DQK*HIDc
    if (i >= (long)Bb*DQK*HIDc) return;
    int e = (int)(i % HIDc);
    int d = (int)((i / HIDc) % DQK);
    int b = (int)(i / ((long)HIDc*DQK));
    long base = (((long)b*Gg*DQK) + d) * HIDc + e;
    const long stride = (long)DQK*HIDc;
    float s = 0.f;
    #pragma unroll
    for (int g = 0; g < Gg; g++) {
        float v = kv[base + g*stride];
        kv[base + g*stride] = s;    // exclusive prefix
        s += v;
    }
}

__global__ void gate_k(const float* __restrict__ att, const float* __restrict__ hid,
                       float* __restrict__ out) {
    long i = (long)blockIdx.x * blockDim.x + threadIdx.x;       // over NT*Ee
    if (i >= (long)NT*Ee) return;
    long t = i / Ee; int e = (int)(i % Ee);
    float av = att[t*HIDc + e];
    float au = att[t*HIDc + Ee + e];
    float v  = hid[t*HIDc + e];
    float u  = hid[t*HIDc + Ee + e];
    out[i] = au * v * (1.f / (1.f + expf(-(av * u))));
}

// ---------------- layernorm (one block per row) ----------------
__global__ void ln_k(const float* __restrict__ in, const float* __restrict__ g,
                     const float* __restrict__ b, float* __restrict__ out, int C) {
    long row = blockIdx.x;
    const float* xr = in + row * C;
    float s = 0.f, s2 = 0.f;
    for (int i = threadIdx.x; i < C; i += blockDim.x) {
        float v = xr[i]; s += v; s2 += v*v;
    }
    #pragma unroll
    for (int o = 16; o; o >>= 1) {
        s  += __shfl_xor_sync(0xffffffffu, s,  o);
        s2 += __shfl_xor_sync(0xffffffffu, s2, o);
    }
    __shared__ float shs[8], shs2[8];
    __shared__ float smu, sinv;
    int w = threadIdx.x >> 5, l = threadIdx.x & 31;
    if (l == 0) { shs[w] = s; shs2[w] = s2; }
    __syncthreads();
    if (threadIdx.x == 0) {
        float ts = 0.f, ts2 = 0.f;
        int nw = blockDim.x >> 5;
        for (int i = 0; i < nw; i++) { ts += shs[i]; ts2 += shs2[i]; }
        float mu = ts / C;
        float var = ts2 / C - mu*mu;
        smu = mu; sinv = rsqrtf(var + 1e-5f);
    }
    __syncthreads();
    float mu = smu, inv = sinv;
    for (int i = threadIdx.x; i < C; i += blockDim.x)
        out[row*C + i] = (xr[i] - mu) * inv * g[i] + b[i];
}

// ---------------- depthwise conv (K=17, SAME) + residual (+ optional extra residual) ----
__global__ void dwconv_k(const float* __restrict__ h, const float* __restrict__ dw,
                         const float* __restrict__ extra, float* __restrict__ out, int C) {
    const int CT = 64, NTile = 128, HALO = 8;
    __shared__ float sh[NTile + 2*HALO][CT];
    __shared__ float sdw[KK][CT];
    int b  = blockIdx.z;
    int n0 = blockIdx.y * NTile;
    int c0 = blockIdx.x * CT;
    const float* base = h + (long)b*Nn*C + c0;
    for (int idx = threadIdx.x; idx < (NTile + 2*HALO)*CT; idx += blockDim.x) {
        int r = idx / CT, c = idx % CT;
        int n = n0 - HALO + r;
        sh[r][c] = (n >= 0 && n < Nn) ? base[(long)n*C + c] : 0.f;
    }
    for (int idx = threadIdx.x; idx < KK*CT; idx += blockDim.x)
        sdw[idx / CT][idx % CT] = dw[(idx / CT)*C + c0 + (idx % CT)];
    __syncthreads();
    for (int idx = threadIdx.x; idx < NTile*CT; idx += blockDim.x) {
        int r = idx / CT, c = idx % CT;
        float acc = sh[r + HALO][c];        // residual h
        #pragma unroll
        for (int k = 0; k < KK; k++)
            acc += sh[r + k][c] * sdw[k][c];
        long o = (long)b*Nn*C + (long)(n0 + r)*C + c0 + c;
        if (extra) acc += extra[o];
        out[o] = acc;
    }
}

// ---------------- batched tiled SGEMM with fused epilogues ----------------
// flags: 1=silu, 2=accumulate into C, 4=score (relu^2 + causal mask), 8=transA, 16=transB
#define F_SILU   1
#define F_ACC    2
#define F_SCORE  4
#define F_TRA    8
#define F_TRB    16

__global__ __launch_bounds__(256) void sgemm_k(
    const float* __restrict__ A, const float* __restrict__ B, float* __restrict__ C,
    int M, int N, int Kd, const float* __restrict__ bias, float alpha, int flags,
    long long sA, long long sB, long long sC)
{
    const int BM = 128, BN = 128, BK = 8;
    __shared__ float As[BK][BM];
    __shared__ float Bs[BK][BN];
    long long bz = blockIdx.z;
    A += bz * sA; B += bz * sB; C += bz * sC;
    int tid  = threadIdx.x;
    int brow = blockIdx.y * BM;
    int bcol = blockIdx.x * BN;
    int tr = (tid / 16) * 8;
    int tc = (tid % 16) * 8;
    float acc[8][8];
    #pragma unroll
    for (int i = 0; i < 8; i++)
        #pragma unroll
        for (int j = 0; j < 8; j++) acc[i][j] = 0.f;

    for (int k0 = 0; k0 < Kd; k0 += BK) {
        // ---- load A tile ----
        if (flags & F_TRA) {
            // A is [Kd, M]
            int kk = tid / 32, mq = (tid % 32) * 4;
            float4 a = *(const float4*)(A + (long)(k0 + kk)*M + brow + mq);
            *(float4*)&As[kk][mq] = a;
        } else {
            // A is [M, Kd]
            int r = tid / 2, kq = (tid % 2) * 4;
            float4 a = *(const float4*)(A + (long)(brow + r)*Kd + k0 + kq);
            As[kq+0][r] = a.x; As[kq+1][r] = a.y; As[kq+2][r] = a.z; As[kq+3][r] = a.w;
        }
        // ---- load B tile ----
        if (flags & F_TRB) {
            // B is [N, Kd]; want Bs[k][n]
            int r = tid / 2, kq = (tid % 2) * 4;
            float4 bv = *(const float4*)(B + (long)(bcol + r)*Kd + k0 + kq);
            Bs[kq+0][r] = bv.x; Bs[kq+1][r] = bv.y; Bs[kq+2][r] = bv.z; Bs[kq+3][r] = bv.w;
        } else {
            // B is [Kd, N]
            int kk = tid / 32, nq = (tid % 32) * 4;
            float4 bv = *(const float4*)(B + (long)(k0 + kk)*N + bcol + nq);
            *(float4*)&Bs[kk][nq] = bv;
        }
        __syncthreads();
        #pragma unroll
        for (int kk = 0; kk < BK; kk++) {
            float ar[8], br[8];
            #pragma unroll
            for (int i = 0; i < 8; i++) ar[i] = As[kk][tr + i];
            #pragma unroll
            for (int j = 0; j < 8; j++) br[j] = Bs[kk][tc + j];
            #pragma unroll
            for (int i = 0; i < 8; i++)
                #pragma unroll
                for (int j = 0; j < 8; j++)
                    acc[i][j] += ar[i] * br[j];
        }
        __syncthreads();
    }
    // ---- epilogue ----
    #pragma unroll
    for (int i = 0; i < 8; i++) {
        int row = brow + tr + i;
        #pragma unroll
        for (int j = 0; j < 8; j++) {
            int col = bcol + tc + j;
            float v = acc[i][j] * alpha;
            if (bias) v += bias[col];
            if (flags & F_SCORE) {
                v = fmaxf(v, 0.f); v = v * v;
                if (col > row) v = 0.f;
            }
            if (flags & F_SILU) v = v / (1.f + expf(-v));
            float* cp = C + (long)row*N + col;
            if (flags & F_ACC) v += *cp;
            *cp = v;
        }
    }
}

// ---------------- launcher ----------------
extern "C" void kernel_launch(void* const* d_in, const int* in_sizes, int n_in,
                              void* d_out, int out_size) {
    const float* x      = (const float*)d_in[0];
    const float* ln_h_g = (const float*)d_in[1];
    const float* ln_h_b = (const float*)d_in[2];
    const float* W_h    = (const float*)d_in[3];
    const float* b_h    = (const float*)d_in[4];
    const float* dw_h   = (const float*)d_in[5];
    const float* ln_qk_g= (const float*)d_in[6];
    const float* ln_qk_b= (const float*)d_in[7];
    const float* W_qk   = (const float*)d_in[8];
    const float* b_qk   = (const float*)d_in[9];
    const float* dw_qk  = (const float*)d_in[10];
    const float* gamma  = (const float*)d_in[11];
    const float* beta   = (const float*)d_in[12];
    const float* ln_o_g = (const float*)d_in[13];
    const float* ln_o_b = (const float*)d_in[14];
    const float* W_o    = (const float*)d_in[15];
    const float* b_o    = (const float*)d_in[16];
    const float* dw_o   = (const float*)d_in[17];
    float* out = (float*)d_out;

    float *bufA, *hid, *ln, *nx, *gate, *kv, *qk, *qk2, *qs, *attn;
    cudaGetSymbolAddress((void**)&bufA, g_bufA);
    cudaGetSymbolAddress((void**)&hid,  g_hid);
    cudaGetSymbolAddress((void**)&ln,   g_ln);
    cudaGetSymbolAddress((void**)&nx,   g_nx);
    cudaGetSymbolAddress((void**)&gate, g_gate);
    cudaGetSymbolAddress((void**)&kv,   g_kv);
    cudaGetSymbolAddress((void**)&qk,   g_qk);
    cudaGetSymbolAddress((void**)&qk2,  g_qk2);
    cudaGetSymbolAddress((void**)&qs,   g_qs);
    cudaGetSymbolAddress((void**)&attn, g_attn);

    const long QS = (long)NT*DQK;   // per-split stride in g_qs

    // 1. token shift: x -> nx
    {
        long n = (long)NT*Dd;
        shift_k<<<(unsigned)((n + 255)/256), 256>>>(x, nx);
    }
    // 2. LN(nx, ln_h) -> ln (512-wide)
    ln_k<<<NT, 256>>>(nx, ln_h_g, ln_h_b, ln, Dd);
    // 3. GEMM1: ln[NT,512] @ W_h[512,2048] + b_h, SiLU -> bufA
    sgemm_k<<<dim3(HIDc/128, NT/128, 1), 256>>>(ln, W_h, bufA, NT, HIDc, Dd,
                                                b_h, 1.f, F_SILU, 0, 0, 0);
    // 4. dwconv residual (C=2048): bufA -> hid
    dwconv_k<<<dim3(HIDc/64, Nn/128, Bb), 256>>>(bufA, dw_h, nullptr, hid, HIDc);
    // 5. LN(nx, ln_qk) -> ln
    ln_k<<<NT, 256>>>(nx, ln_qk_g, ln_qk_b, ln, Dd);
    // 6. GEMM2: ln @ W_qk[512,128] + b_qk, SiLU -> qk
    sgemm_k<<<dim3(DQK/128, NT/128, 1), 256>>>(ln, W_qk, qk, NT, DQK, Dd,
                                               b_qk, 1.f, F_SILU, 0, 0, 0);
    // 7. dwconv residual (C=128): qk -> qk2
    dwconv_k<<<dim3(DQK/64, Nn/128, Bb), 256>>>(qk, dw_qk, nullptr, qk2, DQK);
    // 8. offset-scale split -> qs[4]
    {
        long n = (long)NT*DQK;
        qsplit_k<<<(unsigned)((n + 255)/256), 256>>>(qk2, gamma, beta, qs);
    }
    // 9. scores: quad_q @ quad_k^T / g, relu^2, causal -> attn   (batched 64)
    sgemm_k<<<dim3(GRP/128, GRP/128, Bb*Gg), 256>>>(
        qs + 0*QS, qs + 2*QS, attn, GRP, GRP, DQK,
        nullptr, 1.f/GRP, F_SCORE | F_TRB,
        (long long)GRP*DQK, (long long)GRP*DQK, (long long)GRP*GRP);
    // 10. quad out: attn @ [v|u] -> bufA (att)
    sgemm_k<<<dim3(HIDc/128, GRP/128, Bb*Gg), 256>>>(
        attn, hid, bufA, GRP, HIDc, GRP,
        nullptr, 1.f, 0,
        (long long)GRP*GRP, (long long)GRP*HIDc, (long long)GRP*HIDc);
    // 11. lin kv: lin_k^T @ [v|u] / g -> kv
    sgemm_k<<<dim3(HIDc/128, DQK/128, Bb*Gg), 256>>>(
        qs + 3*QS, hid, kv, DQK, HIDc, GRP,
        nullptr, 1.f/GRP, F_TRA,
        (long long)GRP*DQK, (long long)GRP*HIDc, (long long)DQK*HIDc);
    // 12. exclusive cumsum over groups (in place)
    {
        long n = (long)Bb*DQK*HIDc;
        cumsum_k<<<(unsigned)((n + 255)/256), 256>>>(kv);
    }
    // 13. lin out: lin_q @ kvcum, accumulate into bufA
    sgemm_k<<<dim3(HIDc/128, GRP/128, Bb*Gg), 256>>>(
        qs + 1*QS, kv, bufA, GRP, HIDc, DQK,
        nullptr, 1.f, F_ACC,
        (long long)GRP*DQK, (long long)DQK*HIDc, (long long)GRP*HIDc);
    // 14. gating -> gate [NT,1024]
    {
        long n = (long)NT*Ee;
        gate_k<<<(unsigned)((n + 255)/256), 256>>>(bufA, hid, gate);
    }
    // 15. LN(gate, ln_o) -> ln (1024-wide)
    ln_k<<<NT, 256>>>(gate, ln_o_g, ln_o_b, ln, 2*Dd);
    // 16. GEMM3: ln[NT,1024] @ W_o[1024,512] + b_o, SiLU -> nx (reuse)
    sgemm_k<<<dim3(Dd/128, NT/128, 1), 256>>>(ln, W_o, nx, NT, Dd, 2*Dd,
                                              b_o, 1.f, F_SILU, 0, 0, 0);
    // 17. dwconv residual (C=512) + x -> out
    dwconv_k<<<dim3(Dd/64, Nn/128, Bb), 256>>>(nx, dw_o, x, out, Dd);
}

// round 2
// speedup vs baseline: 1.0006x; 1.0006x over previous
#include <cuda_runtime.h>
#include <cstdint>

// ---------------- problem constants ----------------
#define Bb    8
#define Nn    2048
#define Dd    512
#define HIDc  2048
#define DQK   128
#define GRP   256
#define Gg    8            // Nn / GRP
#define NT    (Bb*Nn)      // 16384 tokens
#define Ee    1024         // HID/2
#define KK    17

// ---------------- scratch (device globals; allocation-free) ----------------
__device__ float g_bufA[(size_t)NT*HIDc];   // h (silu out), later att_v|att_u
__device__ float g_hid [(size_t)NT*HIDc];   // v|u after conv
__device__ float g_ln  [(size_t)NT*1024];   // LN outputs (512- or 1024-wide)
__device__ float g_nx  [(size_t)NT*Dd];     // shifted x; later o_pre (silu out)
__device__ float g_gate[(size_t)NT*Ee];     // gated out
__device__ float g_kv  [(size_t)Bb*Gg*DQK*HIDc]; // lin kv|ku, cumsummed in place
__device__ float g_qk  [(size_t)NT*DQK];    // qk pre-conv
__device__ float g_qk2 [(size_t)NT*DQK];    // qk post-conv
__device__ float g_qs  [(size_t)4*NT*DQK];  // quad_q, lin_q, quad_k, lin_k
__device__ float g_attn[(size_t)Bb*Gg*GRP*GRP];

// ---------------- elementwise kernels ----------------
__global__ void shift_k(const float* __restrict__ x, float* __restrict__ nx) {
    long i = (long)blockIdx.x * blockDim.x + threadIdx.x;
    if (i >= (long)NT*Dd) return;
    int c = (int)(i % Dd);
    long t = i / Dd;
    int n = (int)(t % Nn);
    float v;
    if (c < Dd/2) v = (n == 0) ? 0.f : x[i - Dd];
    else          v = x[i];
    nx[i] = v;
}

__global__ void qsplit_k(const float* __restrict__ qk, const float* __restrict__ gamma,
                         const float* __restrict__ beta, float* __restrict__ qs) {
    long i = (long)blockIdx.x * blockDim.x + threadIdx.x;
    if (i >= (long)NT*DQK) return;
    int d = (int)(i % DQK);
    float v = qk[i];
    #pragma unroll
    for (int s = 0; s < 4; s++)
        qs[(long)s*NT*DQK + i] = v * gamma[s*DQK + d] + beta[s*DQK + d];
}

__global__ void cumsum_k(float* __restrict__ kv) {
    long i = (long)blockIdx.x * blockDim.x + threadIdx.x;       // over Bb*DQK*HIDc
    if (i >= (long)Bb*DQK*HIDc) return;
    int e = (int)(i % HIDc);
    int d = (int)((i / HIDc) % DQK);
    int b = (int)(i / ((long)HIDc*DQK));
    long base = (((long)b*Gg*DQK) + d) * HIDc + e;
    const long stride = (long)DQK*HIDc;
    float s = 0.f;
    #pragma unroll
    for (int g = 0; g < Gg; g++) {
        float v = kv[base + g*stride];
        kv[base + g*stride] = s;    // exclusive prefix
        s += v;
    }
}

__global__ void gate_k(const float* __restrict__ att, const float* __restrict__ hid,
                       float* __restrict__ out) {
    long i = (long)blockIdx.x * blockDim.x + threadIdx.x;       // over NT*Ee
    if (i >= (long)NT*Ee) return;
    long t = i / Ee; int e = (int)(i % Ee);
    float av = att[t*HIDc + e];
    float au = att[t*HIDc + Ee + e];
    float v  = hid[t*HIDc + e];
    float u  = hid[t*HIDc + Ee + e];
    out[i] = au * v * (1.f / (1.f + expf(-(av * u))));
}

// ---------------- layernorm (one block per row) ----------------
__global__ void ln_k(const float* __restrict__ in, const float* __restrict__ g,
                     const float* __restrict__ b, float* __restrict__ out, int C) {
    long row = blockIdx.x;
    const float* xr = in + row * C;
    float s = 0.f, s2 = 0.f;
    for (int i = threadIdx.x; i < C; i += blockDim.x) {
        float v = xr[i]; s += v; s2 += v*v;
    }
    #pragma unroll
    for (int o = 16; o; o >>= 1) {
        s  += __shfl_xor_sync(0xffffffffu, s,  o);
        s2 += __shfl_xor_sync(0xffffffffu, s2, o);
    }
    __shared__ float shs[8], shs2[8];
    __shared__ float smu, sinv;
    int w = threadIdx.x >> 5, l = threadIdx.x & 31;
    if (l == 0) { shs[w] = s; shs2[w] = s2; }
    __syncthreads();
    if (threadIdx.x == 0) {
        float ts = 0.f, ts2 = 0.f;
        int nw = blockDim.x >> 5;
        for (int i = 0; i < nw; i++) { ts += shs[i]; ts2 += shs2[i]; }
        float mu = ts / C;
        float var = ts2 / C - mu*mu;
        smu = mu; sinv = rsqrtf(var + 1e-5f);
    }
    __syncthreads();
    float mu = smu, inv = sinv;
    for (int i = threadIdx.x; i < C; i += blockDim.x)
        out[row*C + i] = (xr[i] - mu) * inv * g[i] + b[i];
}

// ---------------- depthwise conv (K=17, SAME) + residual (+ optional extra residual) ----
__global__ void dwconv_k(const float* __restrict__ h, const float* __restrict__ dw,
                         const float* __restrict__ extra, float* __restrict__ out, int C) {
    const int CT = 64, NTile = 128, HALO = 8;
    __shared__ float sh[NTile + 2*HALO][CT];
    __shared__ float sdw[KK][CT];
    int b  = blockIdx.z;
    int n0 = blockIdx.y * NTile;
    int c0 = blockIdx.x * CT;
    const float* base = h + (long)b*Nn*C + c0;
    for (int idx = threadIdx.x; idx < (NTile + 2*HALO)*CT; idx += blockDim.x) {
        int r = idx / CT, c = idx % CT;
        int n = n0 - HALO + r;
        sh[r][c] = (n >= 0 && n < Nn) ? base[(long)n*C + c] : 0.f;
    }
    for (int idx = threadIdx.x; idx < KK*CT; idx += blockDim.x)
        sdw[idx / CT][idx % CT] = dw[(idx / CT)*C + c0 + (idx % CT)];
    __syncthreads();
    for (int idx = threadIdx.x; idx < NTile*CT; idx += blockDim.x) {
        int r = idx / CT, c = idx % CT;
        float acc = sh[r + HALO][c];        // residual h
        #pragma unroll
        for (int k = 0; k < KK; k++)
            acc += sh[r + k][c] * sdw[k][c];
        long o = (long)b*Nn*C + (long)(n0 + r)*C + c0 + c;
        if (extra) acc += extra[o];
        out[o] = acc;
    }
}

// ---------------- batched tiled SGEMM with fused epilogues ----------------
// flags: 1=silu, 2=accumulate into C, 4=score (relu^2 + causal mask), 8=transA, 16=transB
#define F_SILU   1
#define F_ACC    2
#define F_SCORE  4
#define F_TRA    8
#define F_TRB    16

__global__ __launch_bounds__(256) void sgemm_k(
    const float* __restrict__ A, const float* __restrict__ B, float* __restrict__ C,
    int M, int N, int Kd, const float* __restrict__ bias, float alpha, int flags,
    long long sA, long long sB, long long sC)
{
    const int BM = 128, BN = 128, BK = 8;
    __shared__ float As[BK][BM];
    __shared__ float Bs[BK][BN];
    long long bz = blockIdx.z;
    A += bz * sA; B += bz * sB; C += bz * sC;
    int tid  = threadIdx.x;
    int brow = blockIdx.y * BM;
    int bcol = blockIdx.x * BN;
    int tr = (tid / 16) * 8;
    int tc = (tid % 16) * 8;
    float acc[8][8];
    #pragma unroll
    for (int i = 0; i < 8; i++)
        #pragma unroll
        for (int j = 0; j < 8; j++) acc[i][j] = 0.f;

    for (int k0 = 0; k0 < Kd; k0 += BK) {
        // ---- load A tile ----
        if (flags & F_TRA) {
            // A is [Kd, M]
            int kk = tid / 32, mq = (tid % 32) * 4;
            float4 a = *(const float4*)(A + (long)(k0 + kk)*M + brow + mq);
            *(float4*)&As[kk][mq] = a;
        } else {
            // A is [M, Kd]
            int r = tid / 2, kq = (tid % 2) * 4;
            float4 a = *(const float4*)(A + (long)(brow + r)*Kd + k0 + kq);
            As[kq+0][r] = a.x; As[kq+1][r] = a.y; As[kq+2][r] = a.z; As[kq+3][r] = a.w;
        }
        // ---- load B tile ----
        if (flags & F_TRB) {
            // B is [N, Kd]; want Bs[k][n]
            int r = tid / 2, kq = (tid % 2) * 4;
            float4 bv = *(const float4*)(B + (long)(bcol + r)*Kd + k0 + kq);
            Bs[kq+0][r] = bv.x; Bs[kq+1][r] = bv.y; Bs[kq+2][r] = bv.z; Bs[kq+3][r] = bv.w;
        } else {
            // B is [Kd, N]
            int kk = tid / 32, nq = (tid % 32) * 4;
            float4 bv = *(const float4*)(B + (long)(k0 + kk)*N + bcol + nq);
            *(float4*)&Bs[kk][nq] = bv;
        }
        __syncthreads();
        #pragma unroll
        for (int kk = 0; kk < BK; kk++) {
            float ar[8], br[8];
            #pragma unroll
            for (int i = 0; i < 8; i++) ar[i] = As[kk][tr + i];
            #pragma unroll
            for (int j = 0; j < 8; j++) br[j] = Bs[kk][tc + j];
            #pragma unroll
            for (int i = 0; i < 8; i++)
                #pragma unroll
                for (int j = 0; j < 8; j++)
                    acc[i][j] += ar[i] * br[j];
        }
        __syncthreads();
    }
    // ---- epilogue ----
    #pragma unroll
    for (int i = 0; i < 8; i++) {
        int row = brow + tr + i;
        #pragma unroll
        for (int j = 0; j < 8; j++) {
            int col = bcol + tc + j;
            float v = acc[i][j] * alpha;
            if (bias) v += bias[col];
            if (flags & F_SCORE) {
                v = fmaxf(v, 0.f); v = v * v;
                if (col > row) v = 0.f;
            }
            if (flags & F_SILU) v = v / (1.f + expf(-v));
            float* cp = C + (long)row*N + col;
            if (flags & F_ACC) v += *cp;
            *cp = v;
        }
    }
}

// ---------------- launcher ----------------
extern "C" void kernel_launch(void* const* d_in, const int* in_sizes, int n_in,
                              void* d_out, int out_size) {
    const float* x      = (const float*)d_in[0];
    const float* ln_h_g = (const float*)d_in[1];
    const float* ln_h_b = (const float*)d_in[2];
    const float* W_h    = (const float*)d_in[3];
    const float* b_h    = (const float*)d_in[4];
    const float* dw_h   = (const float*)d_in[5];
    const float* ln_qk_g= (const float*)d_in[6];
    const float* ln_qk_b= (const float*)d_in[7];
    const float* W_qk   = (const float*)d_in[8];
    const float* b_qk   = (const float*)d_in[9];
    const float* dw_qk  = (const float*)d_in[10];
    const float* gamma  = (const float*)d_in[11];
    const float* beta   = (const float*)d_in[12];
    const float* ln_o_g = (const float*)d_in[13];
    const float* ln_o_b = (const float*)d_in[14];
    const float* W_o    = (const float*)d_in[15];
    const float* b_o    = (const float*)d_in[16];
    const float* dw_o   = (const float*)d_in[17];
    float* out = (float*)d_out;

    float *bufA, *hid, *ln, *nx, *gate, *kv, *qk, *qk2, *qs, *attn;
    cudaGetSymbolAddress((void**)&bufA, g_bufA);
    cudaGetSymbolAddress((void**)&hid,  g_hid);
    cudaGetSymbolAddress((void**)&ln,   g_ln);
    cudaGetSymbolAddress((void**)&nx,   g_nx);
    cudaGetSymbolAddress((void**)&gate, g_gate);
    cudaGetSymbolAddress((void**)&kv,   g_kv);
    cudaGetSymbolAddress((void**)&qk,   g_qk);
    cudaGetSymbolAddress((void**)&qk2,  g_qk2);
    cudaGetSymbolAddress((void**)&qs,   g_qs);
    cudaGetSymbolAddress((void**)&attn, g_attn);

    const long QS = (long)NT*DQK;   // per-split stride in g_qs

    // 1. token shift: x -> nx
    {
        long n = (long)NT*Dd;
        shift_k<<<(unsigned)((n + 255)/256), 256>>>(x, nx);
    }
    // 2. LN(nx, ln_h) -> ln (512-wide)
    ln_k<<<NT, 256>>>(nx, ln_h_g, ln_h_b, ln, Dd);
    // 3. GEMM1: ln[NT,512] @ W_h[512,2048] + b_h, SiLU -> bufA
    sgemm_k<<<dim3(HIDc/128, NT/128, 1), 256>>>(ln, W_h, bufA, NT, HIDc, Dd,
                                                b_h, 1.f, F_SILU, 0, 0, 0);
    // 4. dwconv residual (C=2048): bufA -> hid
    dwconv_k<<<dim3(HIDc/64, Nn/128, Bb), 256>>>(bufA, dw_h, nullptr, hid, HIDc);
    // 5. LN(nx, ln_qk) -> ln
    ln_k<<<NT, 256>>>(nx, ln_qk_g, ln_qk_b, ln, Dd);
    // 6. GEMM2: ln @ W_qk[512,128] + b_qk, SiLU -> qk
    sgemm_k<<<dim3(DQK/128, NT/128, 1), 256>>>(ln, W_qk, qk, NT, DQK, Dd,
                                               b_qk, 1.f, F_SILU, 0, 0, 0);
    // 7. dwconv residual (C=128): qk -> qk2
    dwconv_k<<<dim3(DQK/64, Nn/128, Bb), 256>>>(qk, dw_qk, nullptr, qk2, DQK);
    // 8. offset-scale split -> qs[4]
    {
        long n = (long)NT*DQK;
        qsplit_k<<<(unsigned)((n + 255)/256), 256>>>(qk2, gamma, beta, qs);
    }
    // 9. scores: quad_q @ quad_k^T / g, relu^2, causal -> attn   (batched 64)
    sgemm_k<<<dim3(GRP/128, GRP/128, Bb*Gg), 256>>>(
        qs + 0*QS, qs + 2*QS, attn, GRP, GRP, DQK,
        nullptr, 1.f/GRP, F_SCORE | F_TRB,
        (long long)GRP*DQK, (long long)GRP*DQK, (long long)GRP*GRP);
    // 10. quad out: attn @ [v|u] -> bufA (att)
    sgemm_k<<<dim3(HIDc/128, GRP/128, Bb*Gg), 256>>>(
        attn, hid, bufA, GRP, HIDc, GRP,
        nullptr, 1.f, 0,
        (long long)GRP*GRP, (long long)GRP*HIDc, (long long)GRP*HIDc);
    // 11. lin kv: lin_k^T @ [v|u] / g -> kv
    sgemm_k<<<dim3(HIDc/128, DQK/128, Bb*Gg), 256>>>(
        qs + 3*QS, hid, kv, DQK, HIDc, GRP,
        nullptr, 1.f/GRP, F_TRA,
        (long long)GRP*DQK, (long long)GRP*HIDc, (long long)DQK*HIDc);
    // 12. exclusive cumsum over groups (in place)
    {
        long n = (long)Bb*DQK*HIDc;
        cumsum_k<<<(unsigned)((n + 255)/256), 256>>>(kv);
    }
    // 13. lin out: lin_q @ kvcum, accumulate into bufA
    sgemm_k<<<dim3(HIDc/128, GRP/128, Bb*Gg), 256>>>(
        qs + 1*QS, kv, bufA, GRP, HIDc, DQK,
        nullptr, 1.f, F_ACC,
        (long long)GRP*DQK, (long long)DQK*HIDc, (long long)GRP*HIDc);
    // 14. gating -> gate [NT,1024]
    {
        long n = (long)NT*Ee;
        gate_k<<<(unsigned)((n + 255)/256), 256>>>(bufA, hid, gate);
    }
    // 15. LN(gate, ln_o) -> ln (1024-wide)
    ln_k<<<NT, 256>>>(gate, ln_o_g, ln_o_b, ln, 2*Dd);
    // 16. GEMM3: ln[NT,1024] @ W_o[1024,512] + b_o, SiLU -> nx (reuse)
    sgemm_k<<<dim3(Dd/128, NT/128, 1), 256>>>(ln, W_o, nx, NT, Dd, 2*Dd,
                                              b_o, 1.f, F_SILU, 0, 0, 0);
    // 17. dwconv residual (C=512) + x -> out
    dwconv_k<<<dim3(Dd/64, Nn/128, Bb), 256>>>(nx, dw_o, x, out, Dd);
}

// round 4
// speedup vs baseline: 2.0223x; 2.0211x over previous
#include <cuda_runtime.h>
#include <cuda_bf16.h>
#include <cstdint>

#define Bb    8
#define Nn    2048
#define Dd    512
#define HIDc  2048
#define DQK   128
#define GRP   256
#define Gg    8
#define NT    (Bb*Nn)
#define Ee    1024
#define KK    17

// ================= warp MMA helpers (sm_80+ portable) =================
__device__ __forceinline__ uint32_t smem_to_u32(const void* p) {
    uint32_t a;
    asm("{ .reg .u64 t; cvta.to.shared.u64 t, %1; cvt.u32.u64 %0, t; }" : "=r"(a) : "l"(p));
    return a;
}
__device__ __forceinline__ void ldsm4(uint32_t* r, uint32_t addr) {
    asm volatile("ldmatrix.sync.aligned.m8n8.x4.shared.b16 {%0,%1,%2,%3}, [%4];"
        : "=r"(r[0]), "=r"(r[1]), "=r"(r[2]), "=r"(r[3]) : "r"(addr));
}
__device__ __forceinline__ void mma16816(float* c, const uint32_t* a, uint32_t b0, uint32_t b1) {
    asm volatile(
        "mma.sync.aligned.m16n8k16.row.col.f32.bf16.bf16.f32 "
        "{%0,%1,%2,%3}, {%4,%5,%6,%7}, {%8,%9}, {%0,%1,%2,%3};"
        : "+f"(c[0]), "+f"(c[1]), "+f"(c[2]), "+f"(c[3])
        : "r"(a[0]), "r"(a[1]), "r"(a[2]), "r"(a[3]), "r"(b0), "r"(b1));
}

#define F_SILU  1
#define F_ACC   2
#define F_SCORE 4
#define F_TRC   8

// ================= scratch pool =================
#define SZF(n) ((size_t)(n)*4)
#define SZB(n) ((size_t)(n)*2)
static constexpr size_t O_NX   = 0;
static constexpr size_t O_LNH  = O_NX   + SZF((size_t)NT*512);
static constexpr size_t O_LNL  = O_LNH  + SZB((size_t)NT*1024);
static constexpr size_t O_WHTH = O_LNL  + SZB((size_t)NT*1024);
static constexpr size_t O_WHTL = O_WHTH + SZB(2048*512);
static constexpr size_t O_WQTH = O_WHTL + SZB(2048*512);
static constexpr size_t O_WQTL = O_WQTH + SZB(128*512);
static constexpr size_t O_WOTH = O_WQTL + SZB(128*512);
static constexpr size_t O_WOTL = O_WOTH + SZB(512*1024);
static constexpr size_t O_BUFA = O_WOTL + SZB(512*1024);
static constexpr size_t O_HID  = O_BUFA + SZF((size_t)NT*2048);
static constexpr size_t O_HTH  = O_HID  + SZF((size_t)NT*2048);
static constexpr size_t O_HTL  = O_HTH  + SZB((size_t)NT*2048);
static constexpr size_t O_QK   = O_HTL  + SZB((size_t)NT*2048);
static constexpr size_t O_QK2  = O_QK   + SZF((size_t)NT*128);
static constexpr size_t O_QQH  = O_QK2  + SZF((size_t)NT*128);
static constexpr size_t O_QQL  = O_QQH  + SZB((size_t)NT*128);
static constexpr size_t O_LQH  = O_QQL  + SZB((size_t)NT*128);
static constexpr size_t O_LQL  = O_LQH  + SZB((size_t)NT*128);
static constexpr size_t O_QKH  = O_LQL  + SZB((size_t)NT*128);
static constexpr size_t O_QKL  = O_QKH  + SZB((size_t)NT*128);
static constexpr size_t O_LKF  = O_QKL  + SZB((size_t)NT*128);
static constexpr size_t O_LKTH = O_LKF  + SZF((size_t)NT*128);
static constexpr size_t O_LKTL = O_LKTH + SZB((size_t)NT*128);
static constexpr size_t O_ATTH = O_LKTL + SZB((size_t)NT*128);
static constexpr size_t O_ATTL = O_ATTH + SZB((size_t)64*256*256);
static constexpr size_t O_KVF  = O_ATTL + SZB((size_t)64*256*256);
static constexpr size_t O_KVH  = O_KVF  + SZF((size_t)64*2048*128);
static constexpr size_t O_KVL  = O_KVH  + SZB((size_t)64*2048*128);
static constexpr size_t O_END  = O_KVL  + SZB((size_t)64*2048*128);
__device__ __align__(1024) unsigned char g_pool[O_END];

__device__ __forceinline__ void bsplit(float v, __nv_bfloat16* h, __nv_bfloat16* l) {
    __nv_bfloat16 hv = __float2bfloat16(v);
    *h = hv;
    *l = __float2bfloat16(v - __bfloat162float(hv));
}

// ================= elementwise / prep kernels =================
__global__ void shift_k(const float* __restrict__ x, float* __restrict__ nx) {
    long i = (long)blockIdx.x * blockDim.x + threadIdx.x;
    if (i >= (long)NT*Dd) return;
    int c = (int)(i % Dd);
    int n = (int)((i / Dd) % Nn);
    nx[i] = (c < Dd/2) ? ((n == 0) ? 0.f : x[i - Dd]) : x[i];
}

__global__ void ln_split_k(const float* __restrict__ in, const float* __restrict__ g,
                           const float* __restrict__ b,
                           __nv_bfloat16* __restrict__ oh, __nv_bfloat16* __restrict__ ol,
                           int C) {
    long row = blockIdx.x;
    const float* xr = in + row * C;
    float s = 0.f, s2 = 0.f;
    for (int i = threadIdx.x; i < C; i += blockDim.x) { float v = xr[i]; s += v; s2 += v*v; }
    #pragma unroll
    for (int o = 16; o; o >>= 1) {
        s  += __shfl_xor_sync(~0u, s,  o);
        s2 += __shfl_xor_sync(~0u, s2, o);
    }
    __shared__ float shs[8], shs2[8], smu, sinv;
    int w = threadIdx.x >> 5, l = threadIdx.x & 31;
    if (l == 0) { shs[w] = s; shs2[w] = s2; }
    __syncthreads();
    if (threadIdx.x == 0) {
        float ts = 0.f, ts2 = 0.f;
        for (int i = 0; i < (int)(blockDim.x >> 5); i++) { ts += shs[i]; ts2 += shs2[i]; }
        float mu = ts / C;
        smu = mu; sinv = rsqrtf(ts2 / C - mu*mu + 1e-5f);
    }
    __syncthreads();
    float mu = smu, inv = sinv;
    for (int i = threadIdx.x; i < C; i += blockDim.x) {
        float v = (xr[i] - mu) * inv * g[i] + b[i];
        bsplit(v, oh + row*C + i, ol + row*C + i);
    }
}

__global__ void trans_split_k(const float* __restrict__ in,
                              __nv_bfloat16* __restrict__ oh, __nv_bfloat16* __restrict__ ol,
                              int R, int C) {
    __shared__ float t[32][33];
    size_t bz = (size_t)blockIdx.z * R * C;
    int c0 = blockIdx.x * 32, r0 = blockIdx.y * 32;
    int tx = threadIdx.x & 31, ty = threadIdx.x >> 5;
    #pragma unroll
    for (int i = ty; i < 32; i += 8)
        t[i][tx] = in[bz + (size_t)(r0 + i)*C + c0 + tx];
    __syncthreads();
    #pragma unroll
    for (int j = ty; j < 32; j += 8) {
        size_t o = bz + (size_t)(c0 + j)*R + r0 + tx;
        bsplit(t[tx][j], oh + o, ol + o);
    }
}

__global__ void dwconv_k(const float* __restrict__ h, const float* __restrict__ dw,
                         const float* __restrict__ extra, float* __restrict__ out, int C) {
    const int CT = 64, NTile = 128, HALO = 8;
    __shared__ float sh[NTile + 2*HALO][CT];
    __shared__ float sdw[KK][CT];
    int b = blockIdx.z, n0 = blockIdx.y * NTile, c0 = blockIdx.x * CT;
    const float* base = h + (long)b*Nn*C + c0;
    for (int idx = threadIdx.x; idx < (NTile + 2*HALO)*CT; idx += blockDim.x) {
        int r = idx / CT, c = idx % CT;
        int n = n0 - HALO + r;
        sh[r][c] = (n >= 0 && n < Nn) ? base[(long)n*C + c] : 0.f;
    }
    for (int idx = threadIdx.x; idx < KK*CT; idx += blockDim.x)
        sdw[idx / CT][idx % CT] = dw[(idx / CT)*C + c0 + (idx % CT)];
    __syncthreads();
    for (int idx = threadIdx.x; idx < NTile*CT; idx += blockDim.x) {
        int r = idx / CT, c = idx % CT;
        float acc = sh[r + HALO][c];
        #pragma unroll
        for (int k = 0; k < KK; k++) acc += sh[r + k][c] * sdw[k][c];
        long o = (long)b*Nn*C + (long)(n0 + r)*C + c0 + c;
        if (extra) acc += extra[o];
        out[o] = acc;
    }
}

__global__ void qsplit_k(const float* __restrict__ qk, const float* __restrict__ gamma,
                         const float* __restrict__ beta,
                         __nv_bfloat16* qqh, __nv_bfloat16* qql,
                         __nv_bfloat16* lqh, __nv_bfloat16* lql,
                         __nv_bfloat16* qkh, __nv_bfloat16* qkl,
                         float* lkf) {
    long i = (long)blockIdx.x * blockDim.x + threadIdx.x;
    if (i >= (long)NT*DQK) return;
    int d = (int)(i & 127);
    float v = qk[i];
    bsplit(v * gamma[0*DQK + d] + beta[0*DQK + d], qqh + i, qql + i);
    bsplit(v * gamma[1*DQK + d] + beta[1*DQK + d], lqh + i, lql + i);
    bsplit(v * gamma[2*DQK + d] + beta[2*DQK + d], qkh + i, qkl + i);
    lkf[i] = v * gamma[3*DQK + d] + beta[3*DQK + d];
}

__global__ void cumsum_split_k(const float* __restrict__ kvf,
                               __nv_bfloat16* __restrict__ oh,
                               __nv_bfloat16* __restrict__ ol) {
    const size_t S = (size_t)2048*128;
    long i = (long)blockIdx.x * blockDim.x + threadIdx.x;
    if (i >= (long)Bb*S) return;
    size_t b = (size_t)i / S, r = (size_t)i % S;
    size_t base = b*Gg*S + r;
    float s = 0.f;
    #pragma unroll
    for (int g = 0; g < Gg; g++) {
        size_t o = base + (size_t)g*S;
        float v = kvf[o];
        bsplit(s, oh + o, ol + o);
        s += v;
    }
}

__global__ void gate_k(const float* __restrict__ att, const float* __restrict__ hid,
                       float* __restrict__ out) {
    long i = (long)blockIdx.x * blockDim.x + threadIdx.x;
    if (i >= (long)NT*Ee) return;
    long t = i / Ee; int e = (int)(i % Ee);
    float av = att[t*HIDc + e];
    float au = att[t*HIDc + Ee + e];
    float v  = hid[t*HIDc + e];
    float u  = hid[t*HIDc + Ee + e];
    out[i] = au * v * (1.f / (1.f + expf(-(av * u))));
}

// ================= HMMA bf16x3 GEMM, 128x128 tile, 256 thr =================
// D[m,n] = sum_k A[m,k]*B[n,k], both K-major bf16 hi/lo.
#define LDA 72   // bf16 elems per smem row (64 data + 8 pad); 144B, 16B aligned

__global__ void __launch_bounds__(256) gemm_k(
    const __nv_bfloat16* __restrict__ Ah, const __nv_bfloat16* __restrict__ Al,
    const __nv_bfloat16* __restrict__ Bh, const __nv_bfloat16* __restrict__ Bl,
    float* C, __nv_bfloat16* Ch, __nv_bfloat16* Cl,
    int M, int N, int Ktot, const float* __restrict__ bias, float alpha, int flags,
    long long sA, long long sB, long long sC)
{
    __shared__ __align__(16) __nv_bfloat16 shA[128*LDA];
    __shared__ __align__(16) __nv_bfloat16 shB[128*LDA];
    int tid = threadIdx.x, lane = tid & 31, wid = tid >> 5;
    int wm = wid & 3, wn = wid >> 2;            // 4 (M) x 2 (N) warps
    int brow = blockIdx.y * 128, bcol = blockIdx.x * 128;
    long long bz = blockIdx.z;
    Ah += bz*sA; Al += bz*sA; Bh += bz*sB; Bl += bz*sB;
    if (C)  C  += bz*sC;
    if (Ch) { Ch += bz*sC; Cl += bz*sC; }

    float acc[2][8][4];
    #pragma unroll
    for (int i = 0; i < 2; i++)
        #pragma unroll
        for (int j = 0; j < 8; j++)
            #pragma unroll
            for (int q = 0; q < 4; q++) acc[i][j][q] = 0.f;

    uint32_t sAu = smem_to_u32(shA), sBu = smem_to_u32(shB);
    // per-lane ldmatrix addresses (constant across k-chunks except kk offset)
    uint32_t aAddrBase = sAu + (uint32_t)(((wm*32 + (lane & 15)) * LDA + (lane >> 4)*8) * 2);
    uint32_t bAddrBase = sBu + (uint32_t)(((wn*64 + ((lane >> 4) & 1)*8 + (lane & 7)) * LDA
                                           + ((lane >> 3) & 1)*8) * 2);
    const int ldr = tid >> 3, lds2 = tid & 7;    // global->smem: row pair base, segment

    const int KC2 = Ktot >> 6;
    const int nit = 3 * KC2;
    for (int it = 0; it < nit; ++it) {
        int pass = it / KC2;
        int k0 = (it - pass*KC2) << 6;
        const __nv_bfloat16* Ap = (pass == 1) ? Al : Ah;
        const __nv_bfloat16* Bp = (pass == 2) ? Bl : Bh;
        #pragma unroll
        for (int e = 0; e < 4; e++) {
            int r = ldr + e*32;
            *(uint4*)((char*)shA + r*144 + lds2*16) =
                *(const uint4*)(Ap + (size_t)(brow + r)*Ktot + k0 + lds2*8);
            *(uint4*)((char*)shB + r*144 + lds2*16) =
                *(const uint4*)(Bp + (size_t)(bcol + r)*Ktot + k0 + lds2*8);
        }
        __syncthreads();
        #pragma unroll
        for (int kk = 0; kk < 4; kk++) {
            uint32_t af[2][4], bfr[4][4];
            #pragma unroll
            for (int i = 0; i < 2; i++)
                ldsm4(af[i], aAddrBase + (uint32_t)((i*16*LDA + kk*16) * 2));
            #pragma unroll
            for (int p = 0; p < 4; p++)
                ldsm4(bfr[p], bAddrBase + (uint32_t)((p*16*LDA + kk*16) * 2));
            #pragma unroll
            for (int i = 0; i < 2; i++)
                #pragma unroll
                for (int j = 0; j < 8; j++)
                    mma16816(acc[i][j], af[i], bfr[j>>1][(j&1)*2], bfr[j>>1][(j&1)*2+1]);
        }
        __syncthreads();
    }

    // ---- epilogue ----
    int g = lane >> 2, c2 = (lane & 3)*2;
    #pragma unroll
    for (int i = 0; i < 2; i++) {
        #pragma unroll
        for (int j = 0; j < 8; j++) {
            #pragma unroll
            for (int rr = 0; rr < 2; rr++) {
                int row = brow + wm*32 + i*16 + g + rr*8;
                int col = bcol + wn*64 + j*8 + c2;
                float v0 = acc[i][j][rr*2+0] * alpha;
                float v1 = acc[i][j][rr*2+1] * alpha;
                if (flags & F_SCORE) {
                    v0 = fmaxf(v0, 0.f); v0 *= v0;
                    v1 = fmaxf(v1, 0.f); v1 *= v1;
                    if (col     > row) v0 = 0.f;
                    if (col + 1 > row) v1 = 0.f;
                    size_t o = (size_t)row*N + col;
                    __nv_bfloat16 h0 = __float2bfloat16(v0);
                    __nv_bfloat16 h1 = __float2bfloat16(v1);
                    Ch[o]   = h0; Cl[o]   = __float2bfloat16(v0 - __bfloat162float(h0));
                    Ch[o+1] = h1; Cl[o+1] = __float2bfloat16(v1 - __bfloat162float(h1));
                } else if (flags & F_TRC) {
                    C[(size_t)col*M + row]     = v0;
                    C[(size_t)(col+1)*M + row] = v1;
                } else {
                    if (bias) { v0 += bias[col]; v1 += bias[col+1]; }
                    if (flags & F_SILU) {
                        v0 = v0 / (1.f + expf(-v0));
                        v1 = v1 / (1.f + expf(-v1));
                    }
                    size_t o = (size_t)row*N + col;
                    if (flags & F_ACC) { v0 += C[o]; v1 += C[o+1]; }
                    *(float2*)(C + o) = make_float2(v0, v1);
                }
            }
        }
    }
}

// ================= launcher =================
extern "C" void kernel_launch(void* const* d_in, const int* in_sizes, int n_in,
                              void* d_out, int out_size) {
    const float* x      = (const float*)d_in[0];
    const float* ln_h_g = (const float*)d_in[1];
    const float* ln_h_b = (const float*)d_in[2];
    const float* W_h    = (const float*)d_in[3];
    const float* b_h    = (const float*)d_in[4];
    const float* dw_h   = (const float*)d_in[5];
    const float* ln_qk_g= (const float*)d_in[6];
    const float* ln_qk_b= (const float*)d_in[7];
    const float* W_qk   = (const float*)d_in[8];
    const float* b_qk   = (const float*)d_in[9];
    const float* dw_qk  = (const float*)d_in[10];
    const float* gamma  = (const float*)d_in[11];
    const float* beta   = (const float*)d_in[12];
    const float* ln_o_g = (const float*)d_in[13];
    const float* ln_o_b = (const float*)d_in[14];
    const float* W_o    = (const float*)d_in[15];
    const float* b_o    = (const float*)d_in[16];
    const float* dw_o   = (const float*)d_in[17];
    float* out = (float*)d_out;

    unsigned char* pool;
    cudaGetSymbolAddress((void**)&pool, g_pool);
    float*         nx   = (float*)(pool + O_NX);
    __nv_bfloat16* lnH  = (__nv_bfloat16*)(pool + O_LNH);
    __nv_bfloat16* lnL  = (__nv_bfloat16*)(pool + O_LNL);
    __nv_bfloat16* whTH = (__nv_bfloat16*)(pool + O_WHTH);
    __nv_bfloat16* whTL = (__nv_bfloat16*)(pool + O_WHTL);
    __nv_bfloat16* wqTH = (__nv_bfloat16*)(pool + O_WQTH);
    __nv_bfloat16* wqTL = (__nv_bfloat16*)(pool + O_WQTL);
    __nv_bfloat16* woTH = (__nv_bfloat16*)(pool + O_WOTH);
    __nv_bfloat16* woTL = (__nv_bfloat16*)(pool + O_WOTL);
    float*         bufA = (float*)(pool + O_BUFA);
    float*         hid  = (float*)(pool + O_HID);
    __nv_bfloat16* hTH  = (__nv_bfloat16*)(pool + O_HTH);
    __nv_bfloat16* hTL  = (__nv_bfloat16*)(pool + O_HTL);
    float*         qk   = (float*)(pool + O_QK);
    float*         qk2  = (float*)(pool + O_QK2);
    __nv_bfloat16* qqH  = (__nv_bfloat16*)(pool + O_QQH);
    __nv_bfloat16* qqL  = (__nv_bfloat16*)(pool + O_QQL);
    __nv_bfloat16* lqH  = (__nv_bfloat16*)(pool + O_LQH);
    __nv_bfloat16* lqL  = (__nv_bfloat16*)(pool + O_LQL);
    __nv_bfloat16* qkH  = (__nv_bfloat16*)(pool + O_QKH);
    __nv_bfloat16* qkL  = (__nv_bfloat16*)(pool + O_QKL);
    float*         lkF  = (float*)(pool + O_LKF);
    __nv_bfloat16* lkTH = (__nv_bfloat16*)(pool + O_LKTH);
    __nv_bfloat16* lkTL = (__nv_bfloat16*)(pool + O_LKTL);
    __nv_bfloat16* attH = (__nv_bfloat16*)(pool + O_ATTH);
    __nv_bfloat16* attL = (__nv_bfloat16*)(pool + O_ATTL);
    float*         kvF  = (float*)(pool + O_KVF);
    __nv_bfloat16* kvH  = (__nv_bfloat16*)(pool + O_KVH);
    __nv_bfloat16* kvL  = (__nv_bfloat16*)(pool + O_KVL);
    float*         gate = kvF;
    float*         opre = nx;

    // 1. token shift
    shift_k<<<(NT*Dd + 255)/256, 256>>>(x, nx);
    // 2. weight transposes -> bf16 hi/lo  [out,in] K-major
    trans_split_k<<<dim3(2048/32, 512/32, 1), 256>>>(W_h,  whTH, whTL, 512, 2048);
    trans_split_k<<<dim3(128/32,  512/32, 1), 256>>>(W_qk, wqTH, wqTL, 512, 128);
    trans_split_k<<<dim3(512/32, 1024/32, 1), 256>>>(W_o,  woTH, woTL, 1024, 512);
    // 3. LN_h -> hi/lo
    ln_split_k<<<NT, 256>>>(nx, ln_h_g, ln_h_b, lnH, lnL, Dd);
    // 4. GEMM1 -> bufA (SiLU)
    gemm_k<<<dim3(16, 128, 1), 256>>>(lnH, lnL, whTH, whTL, bufA, nullptr, nullptr,
        NT, HIDc, Dd, b_h, 1.f, F_SILU, 0, 0, 0);
    // 5. dwconv -> hid
    dwconv_k<<<dim3(32, 16, Bb), 256>>>(bufA, dw_h, nullptr, hid, HIDc);
    // 6. hid per-group transpose -> hT [bg,2048,256]
    trans_split_k<<<dim3(64, 8, 64), 256>>>(hid, hTH, hTL, 256, 2048);
    // 7. LN_qk -> hi/lo
    ln_split_k<<<NT, 256>>>(nx, ln_qk_g, ln_qk_b, lnH, lnL, Dd);
    // 8. GEMM2 -> qk (SiLU)
    gemm_k<<<dim3(1, 128, 1), 256>>>(lnH, lnL, wqTH, wqTL, qk, nullptr, nullptr,
        NT, DQK, Dd, b_qk, 1.f, F_SILU, 0, 0, 0);
    // 9. dwconv -> qk2
    dwconv_k<<<dim3(2, 16, Bb), 256>>>(qk, dw_qk, nullptr, qk2, DQK);
    // 10. offset-scale split
    qsplit_k<<<(NT*DQK + 255)/256, 256>>>(qk2, gamma, beta, qqH, qqL, lqH, lqL, qkH, qkL, lkF);
    // 11. lin_k per-group transpose -> lkT [bg,128,256]
    trans_split_k<<<dim3(4, 8, 64), 256>>>(lkF, lkTH, lkTL, 256, 128);
    // 12. scores -> attH/attL (relu^2 causal, bf16 split)
    gemm_k<<<dim3(2, 2, 64), 256>>>(qqH, qqL, qkH, qkL, nullptr, attH, attL,
        GRP, GRP, DQK, nullptr, 1.f/GRP, F_SCORE,
        (long long)GRP*DQK, (long long)GRP*DQK, (long long)GRP*GRP);
    // 13. quad out: attn @ hidT^T -> bufA
    gemm_k<<<dim3(16, 2, 64), 256>>>(attH, attL, hTH, hTL, bufA, nullptr, nullptr,
        GRP, HIDc, GRP, nullptr, 1.f, 0,
        (long long)GRP*GRP, (long long)HIDc*GRP, (long long)GRP*HIDc);
    // 14. lin kv: lkT @ hidT^T / g -> kvF transposed [bg,2048,128]
    gemm_k<<<dim3(16, 1, 64), 256>>>(lkTH, lkTL, hTH, hTL, kvF, nullptr, nullptr,
        DQK, HIDc, GRP, nullptr, 1.f/GRP, F_TRC,
        (long long)DQK*GRP, (long long)HIDc*GRP, (long long)HIDc*DQK);
    // 15. exclusive group cumsum -> kvH/kvL
    cumsum_split_k<<<(int)(((size_t)Bb*2048*128 + 255)/256), 256>>>(kvF, kvH, kvL);
    // 16. lin out: lin_q @ kvT^T, accumulate into bufA
    gemm_k<<<dim3(16, 2, 64), 256>>>(lqH, lqL, kvH, kvL, bufA, nullptr, nullptr,
        GRP, HIDc, DQK, nullptr, 1.f, F_ACC,
        (long long)GRP*DQK, (long long)HIDc*DQK, (long long)GRP*HIDc);
    // 17. gating
    gate_k<<<(NT*Ee + 255)/256, 256>>>(bufA, hid, gate);
    // 18. LN_o -> hi/lo (1024 wide)
    ln_split_k<<<NT, 256>>>(gate, ln_o_g, ln_o_b, lnH, lnL, 2*Dd);
    // 19. GEMM3 -> opre (SiLU)
    gemm_k<<<dim3(4, 128, 1), 256>>>(lnH, lnL, woTH, woTL, opre, nullptr, nullptr,
        NT, Dd, 2*Dd, b_o, 1.f, F_SILU, 0, 0, 0);
    // 20. dwconv + x residual -> out
    dwconv_k<<<dim3(8, 16, Bb), 256>>>(opre, dw_o, x, out, Dd);
}

// round 5
// speedup vs baseline: 2.3294x; 1.1518x over previous
#include <cuda_runtime.h>
#include <cuda_bf16.h>
#include <cstdint>

#define Bb    8
#define Nn    2048
#define Dd    512
#define HIDc  2048
#define DQK   128
#define GRP   256
#define Gg    8
#define NT    (Bb*Nn)
#define Ee    1024
#define KK    17

// ================= warp MMA / async helpers (sm_80+ portable) =================
__device__ __forceinline__ uint32_t smem_to_u32(const void* p) {
    uint32_t a;
    asm("{ .reg .u64 t; cvta.to.shared.u64 t, %1; cvt.u32.u64 %0, t; }" : "=r"(a) : "l"(p));
    return a;
}
__device__ __forceinline__ void ldsm4(uint32_t* r, uint32_t addr) {
    asm volatile("ldmatrix.sync.aligned.m8n8.x4.shared.b16 {%0,%1,%2,%3}, [%4];"
        : "=r"(r[0]), "=r"(r[1]), "=r"(r[2]), "=r"(r[3]) : "r"(addr));
}
__device__ __forceinline__ void mma16816(float* c, const uint32_t* a, uint32_t b0, uint32_t b1) {
    asm volatile(
        "mma.sync.aligned.m16n8k16.row.col.f32.bf16.bf16.f32 "
        "{%0,%1,%2,%3}, {%4,%5,%6,%7}, {%8,%9}, {%0,%1,%2,%3};"
        : "+f"(c[0]), "+f"(c[1]), "+f"(c[2]), "+f"(c[3])
        : "r"(a[0]), "r"(a[1]), "r"(a[2]), "r"(a[3]), "r"(b0), "r"(b1));
}
__device__ __forceinline__ void cp16(uint32_t dst, const void* src) {
    asm volatile("cp.async.cg.shared.global [%0], [%1], 16;" :: "r"(dst), "l"(src));
}
#define CP_COMMIT() asm volatile("cp.async.commit_group;" ::: "memory")
#define CP_WAIT(N)  asm volatile("cp.async.wait_group %0;" :: "n"(N) : "memory")

#define F_SILU  1
#define F_ACC   2
#define F_SCORE 4
#define F_TRC   8

// ================= scratch pool =================
#define SZF(n) ((size_t)(n)*4)
#define SZB(n) ((size_t)(n)*2)
static constexpr size_t O_NX   = 0;
static constexpr size_t O_LNH  = O_NX   + SZF((size_t)NT*512);
static constexpr size_t O_LNL  = O_LNH  + SZB((size_t)NT*1024);
static constexpr size_t O_WHTH = O_LNL  + SZB((size_t)NT*1024);
static constexpr size_t O_WHTL = O_WHTH + SZB(2048*512);
static constexpr size_t O_WQTH = O_WHTL + SZB(2048*512);
static constexpr size_t O_WQTL = O_WQTH + SZB(128*512);
static constexpr size_t O_WOTH = O_WQTL + SZB(128*512);
static constexpr size_t O_WOTL = O_WOTH + SZB(512*1024);
static constexpr size_t O_BUFA = O_WOTL + SZB(512*1024);
static constexpr size_t O_HID  = O_BUFA + SZF((size_t)NT*2048);
static constexpr size_t O_HTH  = O_HID  + SZF((size_t)NT*2048);
static constexpr size_t O_HTL  = O_HTH  + SZB((size_t)NT*2048);
static constexpr size_t O_QK   = O_HTL  + SZB((size_t)NT*2048);
static constexpr size_t O_QK2  = O_QK   + SZF((size_t)NT*128);
static constexpr size_t O_QQH  = O_QK2  + SZF((size_t)NT*128);
static constexpr size_t O_QQL  = O_QQH  + SZB((size_t)NT*128);
static constexpr size_t O_LQH  = O_QQL  + SZB((size_t)NT*128);
static constexpr size_t O_LQL  = O_LQH  + SZB((size_t)NT*128);
static constexpr size_t O_QKH  = O_LQL  + SZB((size_t)NT*128);
static constexpr size_t O_QKL  = O_QKH  + SZB((size_t)NT*128);
static constexpr size_t O_LKF  = O_QKL  + SZB((size_t)NT*128);
static constexpr size_t O_LKTH = O_LKF  + SZF((size_t)NT*128);
static constexpr size_t O_LKTL = O_LKTH + SZB((size_t)NT*128);
static constexpr size_t O_ATTH = O_LKTL + SZB((size_t)NT*128);
static constexpr size_t O_ATTL = O_ATTH + SZB((size_t)64*256*256);
static constexpr size_t O_KVF  = O_ATTL + SZB((size_t)64*256*256);
static constexpr size_t O_KVH  = O_KVF  + SZF((size_t)64*2048*128);
static constexpr size_t O_KVL  = O_KVH  + SZB((size_t)64*2048*128);
static constexpr size_t O_END  = O_KVL  + SZB((size_t)64*2048*128);
__device__ __align__(1024) unsigned char g_pool[O_END];

__device__ __forceinline__ void bsplit(float v, __nv_bfloat16* h, __nv_bfloat16* l) {
    __nv_bfloat16 hv = __float2bfloat16(v);
    *h = hv;
    *l = __float2bfloat16(v - __bfloat162float(hv));
}

// ================= elementwise / prep kernels =================
__global__ void shift_k(const float4* __restrict__ x, float4* __restrict__ nx) {
    long i = (long)blockIdx.x * blockDim.x + threadIdx.x;   // over NT*Dd/4
    if (i >= (long)NT*(Dd/4)) return;
    int c4 = (int)(i % (Dd/4));
    int n  = (int)((i / (Dd/4)) % Nn);
    if (c4 < Dd/8) nx[i] = (n == 0) ? make_float4(0,0,0,0) : x[i - Dd/4];
    else           nx[i] = x[i];
}

__global__ void ln_split_k(const float* __restrict__ in, const float* __restrict__ g,
                           const float* __restrict__ b,
                           __nv_bfloat16* __restrict__ oh, __nv_bfloat16* __restrict__ ol,
                           int C) {
    long row = blockIdx.x;
    const float* xr = in + row * C;
    float s = 0.f, s2 = 0.f;
    for (int i = threadIdx.x; i < C; i += blockDim.x) { float v = xr[i]; s += v; s2 += v*v; }
    #pragma unroll
    for (int o = 16; o; o >>= 1) {
        s  += __shfl_xor_sync(~0u, s,  o);
        s2 += __shfl_xor_sync(~0u, s2, o);
    }
    __shared__ float shs[8], shs2[8], smu, sinv;
    int w = threadIdx.x >> 5, l = threadIdx.x & 31;
    if (l == 0) { shs[w] = s; shs2[w] = s2; }
    __syncthreads();
    if (threadIdx.x == 0) {
        float ts = 0.f, ts2 = 0.f;
        for (int i = 0; i < (int)(blockDim.x >> 5); i++) { ts += shs[i]; ts2 += shs2[i]; }
        float mu = ts / C;
        smu = mu; sinv = rsqrtf(ts2 / C - mu*mu + 1e-5f);
    }
    __syncthreads();
    float mu = smu, inv = sinv;
    for (int i = threadIdx.x; i < C; i += blockDim.x) {
        float v = (xr[i] - mu) * inv * g[i] + b[i];
        bsplit(v, oh + row*C + i, ol + row*C + i);
    }
}

// fused gating + LN(1024) -> bf16 hi/lo
__global__ void gate_ln_k(const float* __restrict__ att, const float* __restrict__ hid,
                          const float* __restrict__ g, const float* __restrict__ b,
                          __nv_bfloat16* __restrict__ oh, __nv_bfloat16* __restrict__ ol) {
    long row = blockIdx.x;
    __shared__ float buf[1024];
    const float* ar = att + row*HIDc;
    const float* hr = hid + row*HIDc;
    float s = 0.f, s2 = 0.f;
    for (int i = threadIdx.x; i < 1024; i += blockDim.x) {
        float av = ar[i], au = ar[Ee + i], v = hr[i], u = hr[Ee + i];
        float val = au * v * (1.f / (1.f + expf(-(av * u))));
        buf[i] = val; s += val; s2 += val*val;
    }
    #pragma unroll
    for (int o = 16; o; o >>= 1) {
        s  += __shfl_xor_sync(~0u, s,  o);
        s2 += __shfl_xor_sync(~0u, s2, o);
    }
    __shared__ float shs[8], shs2[8], smu, sinv;
    int w = threadIdx.x >> 5, l = threadIdx.x & 31;
    if (l == 0) { shs[w] = s; shs2[w] = s2; }
    __syncthreads();
    if (threadIdx.x == 0) {
        float ts = 0.f, ts2 = 0.f;
        for (int i = 0; i < (int)(blockDim.x >> 5); i++) { ts += shs[i]; ts2 += shs2[i]; }
        float mu = ts / 1024.f;
        smu = mu; sinv = rsqrtf(ts2 / 1024.f - mu*mu + 1e-5f);
    }
    __syncthreads();
    float mu = smu, inv = sinv;
    for (int i = threadIdx.x; i < 1024; i += blockDim.x) {
        float v = (buf[i] - mu) * inv * g[i] + b[i];
        bsplit(v, oh + row*1024 + i, ol + row*1024 + i);
    }
}

__global__ void trans_split_k(const float* __restrict__ in,
                              __nv_bfloat16* __restrict__ oh, __nv_bfloat16* __restrict__ ol,
                              int R, int C) {
    __shared__ float t[32][33];
    size_t bz = (size_t)blockIdx.z * R * C;
    int c0 = blockIdx.x * 32, r0 = blockIdx.y * 32;
    int tx = threadIdx.x & 31, ty = threadIdx.x >> 5;
    #pragma unroll
    for (int i = ty; i < 32; i += 8)
        t[i][tx] = in[bz + (size_t)(r0 + i)*C + c0 + tx];
    __syncthreads();
    #pragma unroll
    for (int j = ty; j < 32; j += 8) {
        size_t o = bz + (size_t)(c0 + j)*R + r0 + tx;
        bsplit(t[tx][j], oh + o, ol + o);
    }
}

// float4-vectorized depthwise conv K=17 + residual (+ optional extra residual)
__global__ void dwconv4_k(const float4* __restrict__ h4, const float* __restrict__ dw,
                          const float4* __restrict__ extra4, float4* __restrict__ out4, int C) {
    const int CT4 = 16, NTile = 128, HALO = 8;
    __shared__ float4 sh[NTile + 2*HALO][CT4];
    __shared__ float4 sdw[KK][CT4];
    int b = blockIdx.z, n0 = blockIdx.y * NTile, c0 = blockIdx.x * CT4;
    int C4 = C >> 2;
    const float4* base = h4 + (size_t)b*Nn*C4 + c0;
    for (int idx = threadIdx.x; idx < (NTile + 2*HALO)*CT4; idx += blockDim.x) {
        int r = idx >> 4, c = idx & 15;
        int n = n0 - HALO + r;
        sh[r][c] = (n >= 0 && n < Nn) ? base[(size_t)n*C4 + c] : make_float4(0,0,0,0);
    }
    for (int idx = threadIdx.x; idx < KK*CT4; idx += blockDim.x) {
        int k = idx >> 4, c = idx & 15;
        const float* w = dw + k*C + (c0 + c)*4;
        sdw[k][c] = make_float4(w[0], w[1], w[2], w[3]);
    }
    __syncthreads();
    for (int idx = threadIdx.x; idx < NTile*CT4; idx += blockDim.x) {
        int r = idx >> 4, c = idx & 15;
        float4 acc = sh[r + HALO][c];
        #pragma unroll
        for (int k = 0; k < KK; k++) {
            float4 a = sh[r + k][c], w = sdw[k][c];
            acc.x += a.x*w.x; acc.y += a.y*w.y; acc.z += a.z*w.z; acc.w += a.w*w.w;
        }
        size_t o = (size_t)b*Nn*C4 + (size_t)(n0 + r)*C4 + c0 + c;
        if (extra4) {
            float4 e = extra4[o];
            acc.x += e.x; acc.y += e.y; acc.z += e.z; acc.w += e.w;
        }
        out4[o] = acc;
    }
}

__global__ void qsplit_k(const float* __restrict__ qk, const float* __restrict__ gamma,
                         const float* __restrict__ beta,
                         __nv_bfloat16* qqh, __nv_bfloat16* qql,
                         __nv_bfloat16* lqh, __nv_bfloat16* lql,
                         __nv_bfloat16* qkh, __nv_bfloat16* qkl,
                         float* lkf) {
    long i = (long)blockIdx.x * blockDim.x + threadIdx.x;
    if (i >= (long)NT*DQK) return;
    int d = (int)(i & 127);
    float v = qk[i];
    bsplit(v * gamma[0*DQK + d] + beta[0*DQK + d], qqh + i, qql + i);
    bsplit(v * gamma[1*DQK + d] + beta[1*DQK + d], lqh + i, lql + i);
    bsplit(v * gamma[2*DQK + d] + beta[2*DQK + d], qkh + i, qkl + i);
    lkf[i] = v * gamma[3*DQK + d] + beta[3*DQK + d];
}

__global__ void cumsum_split_k(const float* __restrict__ kvf,
                               __nv_bfloat16* __restrict__ oh,
                               __nv_bfloat16* __restrict__ ol) {
    const size_t S = (size_t)2048*128;
    long i = (long)blockIdx.x * blockDim.x + threadIdx.x;
    if (i >= (long)Bb*S) return;
    size_t b = (size_t)i / S, r = (size_t)i % S;
    size_t base = b*Gg*S + r;
    float s = 0.f;
    #pragma unroll
    for (int g = 0; g < Gg; g++) {
        size_t o = base + (size_t)g*S;
        float v = kvf[o];
        bsplit(s, oh + o, ol + o);
        s += v;
    }
}

// ================= HMMA bf16x3 GEMM, 128x128 tile, cp.async 2-stage =================
#define LDA 72            // bf16 elems per smem row (64 data + 8 pad) = 144 B
#define STG_BYTES 36864   // one stage: A (18432) + B (18432)
#define GSMEM (2*STG_BYTES)

__global__ void __launch_bounds__(256) gemm_k(
    const __nv_bfloat16* __restrict__ Ah, const __nv_bfloat16* __restrict__ Al,
    const __nv_bfloat16* __restrict__ Bh, const __nv_bfloat16* __restrict__ Bl,
    float* C, __nv_bfloat16* Ch, __nv_bfloat16* Cl,
    int M, int N, int Ktot, const float* __restrict__ bias, float alpha, int flags,
    long long sA, long long sB, long long sC)
{
    extern __shared__ __align__(16) unsigned char smem[];
    uint32_t sbase = smem_to_u32(smem);
    int tid = threadIdx.x, lane = tid & 31, wid = tid >> 5;
    int wm = wid & 3, wn = wid >> 2;            // 4 (M) x 2 (N) warps
    int brow = blockIdx.y * 128, bcol = blockIdx.x * 128;
    long long bz = blockIdx.z;
    Ah += bz*sA; Al += bz*sA; Bh += bz*sB; Bl += bz*sB;
    if (C)  C  += bz*sC;
    if (Ch) { Ch += bz*sC; Cl += bz*sC; }

    float acc[2][8][4];
    #pragma unroll
    for (int i = 0; i < 2; i++)
        #pragma unroll
        for (int j = 0; j < 8; j++)
            #pragma unroll
            for (int q = 0; q < 4; q++) acc[i][j][q] = 0.f;

    // ldmatrix per-lane byte offsets within a stage
    uint32_t aOff = (uint32_t)(((wm*32 + (lane & 15)) * LDA + (lane >> 4)*8) * 2);
    uint32_t bOff = (uint32_t)(((wn*64 + ((lane >> 4) & 1)*8 + (lane & 7)) * LDA
                                + ((lane >> 3) & 1)*8) * 2) + 18432;
    const int ldr = tid >> 3, lds2 = tid & 7;

    const int KC2 = Ktot >> 6;
    const int nit = 3 * KC2;

    // stage-issue helper (4 A rows + 4 B rows of 16B per thread)
    auto issue = [&](int it) {
        int pass = it / KC2;
        int k0 = (it - pass*KC2) << 6;
        const __nv_bfloat16* Ap = (pass == 1) ? Al : Ah;
        const __nv_bfloat16* Bp = (pass == 2) ? Bl : Bh;
        uint32_t sa = sbase + (uint32_t)(it & 1)*STG_BYTES;
        #pragma unroll
        for (int e = 0; e < 4; e++) {
            int r = ldr + e*32;
            cp16(sa + (uint32_t)(r*144 + lds2*16),
                 Ap + (size_t)(brow + r)*Ktot + k0 + lds2*8);
            cp16(sa + 18432u + (uint32_t)(r*144 + lds2*16),
                 Bp + (size_t)(bcol + r)*Ktot + k0 + lds2*8);
        }
        CP_COMMIT();
    };

    issue(0);
    for (int it = 0; it < nit; ++it) {
        if (it + 1 < nit) { issue(it + 1); CP_WAIT(1); }
        else              { CP_WAIT(0); }
        __syncthreads();
        uint32_t stg = sbase + (uint32_t)(it & 1)*STG_BYTES;
        uint32_t aB = stg + aOff, bB = stg + bOff;
        #pragma unroll
        for (int kk = 0; kk < 4; kk++) {
            uint32_t af[2][4], bfr[4][4];
            #pragma unroll
            for (int i = 0; i < 2; i++)
                ldsm4(af[i], aB + (uint32_t)((i*16*LDA + kk*16) * 2));
            #pragma unroll
            for (int p = 0; p < 4; p++)
                ldsm4(bfr[p], bB + (uint32_t)((p*16*LDA + kk*16) * 2));
            #pragma unroll
            for (int i = 0; i < 2; i++)
                #pragma unroll
                for (int j = 0; j < 8; j++)
                    mma16816(acc[i][j], af[i], bfr[j>>1][(j&1)*2], bfr[j>>1][(j&1)*2+1]);
        }
        __syncthreads();
    }

    // ---- epilogue ----
    int g = lane >> 2, c2 = (lane & 3)*2;
    #pragma unroll
    for (int i = 0; i < 2; i++) {
        #pragma unroll
        for (int j = 0; j < 8; j++) {
            #pragma unroll
            for (int rr = 0; rr < 2; rr++) {
                int row = brow + wm*32 + i*16 + g + rr*8;
                int col = bcol + wn*64 + j*8 + c2;
                float v0 = acc[i][j][rr*2+0] * alpha;
                float v1 = acc[i][j][rr*2+1] * alpha;
                if (flags & F_SCORE) {
                    v0 = fmaxf(v0, 0.f); v0 *= v0;
                    v1 = fmaxf(v1, 0.f); v1 *= v1;
                    if (col     > row) v0 = 0.f;
                    if (col + 1 > row) v1 = 0.f;
                    size_t o = (size_t)row*N + col;
                    __nv_bfloat16 h0 = __float2bfloat16(v0);
                    __nv_bfloat16 h1 = __float2bfloat16(v1);
                    Ch[o]   = h0; Cl[o]   = __float2bfloat16(v0 - __bfloat162float(h0));
                    Ch[o+1] = h1; Cl[o+1] = __float2bfloat16(v1 - __bfloat162float(h1));
                } else if (flags & F_TRC) {
                    C[(size_t)col*M + row]     = v0;
                    C[(size_t)(col+1)*M + row] = v1;
                } else {
                    if (bias) { v0 += bias[col]; v1 += bias[col+1]; }
                    if (flags & F_SILU) {
                        v0 = v0 / (1.f + expf(-v0));
                        v1 = v1 / (1.f + expf(-v1));
                    }
                    size_t o = (size_t)row*N + col;
                    if (flags & F_ACC) { v0 += C[o]; v1 += C[o+1]; }
                    *(float2*)(C + o) = make_float2(v0, v1);
                }
            }
        }
    }
}

// ================= launcher =================
extern "C" void kernel_launch(void* const* d_in, const int* in_sizes, int n_in,
                              void* d_out, int out_size) {
    const float* x      = (const float*)d_in[0];
    const float* ln_h_g = (const float*)d_in[1];
    const float* ln_h_b = (const float*)d_in[2];
    const float* W_h    = (const float*)d_in[3];
    const float* b_h    = (const float*)d_in[4];
    const float* dw_h   = (const float*)d_in[5];
    const float* ln_qk_g= (const float*)d_in[6];
    const float* ln_qk_b= (const float*)d_in[7];
    const float* W_qk   = (const float*)d_in[8];
    const float* b_qk   = (const float*)d_in[9];
    const float* dw_qk  = (const float*)d_in[10];
    const float* gamma  = (const float*)d_in[11];
    const float* beta   = (const float*)d_in[12];
    const float* ln_o_g = (const float*)d_in[13];
    const float* ln_o_b = (const float*)d_in[14];
    const float* W_o    = (const float*)d_in[15];
    const float* b_o    = (const float*)d_in[16];
    const float* dw_o   = (const float*)d_in[17];
    float* out = (float*)d_out;

    unsigned char* pool;
    cudaGetSymbolAddress((void**)&pool, g_pool);
    float*         nx   = (float*)(pool + O_NX);
    __nv_bfloat16* lnH  = (__nv_bfloat16*)(pool + O_LNH);
    __nv_bfloat16* lnL  = (__nv_bfloat16*)(pool + O_LNL);
    __nv_bfloat16* whTH = (__nv_bfloat16*)(pool + O_WHTH);
    __nv_bfloat16* whTL = (__nv_bfloat16*)(pool + O_WHTL);
    __nv_bfloat16* wqTH = (__nv_bfloat16*)(pool + O_WQTH);
    __nv_bfloat16* wqTL = (__nv_bfloat16*)(pool + O_WQTL);
    __nv_bfloat16* woTH = (__nv_bfloat16*)(pool + O_WOTH);
    __nv_bfloat16* woTL = (__nv_bfloat16*)(pool + O_WOTL);
    float*         bufA = (float*)(pool + O_BUFA);
    float*         hid  = (float*)(pool + O_HID);
    __nv_bfloat16* hTH  = (__nv_bfloat16*)(pool + O_HTH);
    __nv_bfloat16* hTL  = (__nv_bfloat16*)(pool + O_HTL);
    float*         qk   = (float*)(pool + O_QK);
    float*         qk2  = (float*)(pool + O_QK2);
    __nv_bfloat16* qqH  = (__nv_bfloat16*)(pool + O_QQH);
    __nv_bfloat16* qqL  = (__nv_bfloat16*)(pool + O_QQL);
    __nv_bfloat16* lqH  = (__nv_bfloat16*)(pool + O_LQH);
    __nv_bfloat16* lqL  = (__nv_bfloat16*)(pool + O_LQL);
    __nv_bfloat16* qkH  = (__nv_bfloat16*)(pool + O_QKH);
    __nv_bfloat16* qkL  = (__nv_bfloat16*)(pool + O_QKL);
    float*         lkF  = (float*)(pool + O_LKF);
    __nv_bfloat16* lkTH = (__nv_bfloat16*)(pool + O_LKTH);
    __nv_bfloat16* lkTL = (__nv_bfloat16*)(pool + O_LKTL);
    __nv_bfloat16* attH = (__nv_bfloat16*)(pool + O_ATTH);
    __nv_bfloat16* attL = (__nv_bfloat16*)(pool + O_ATTL);
    float*         kvF  = (float*)(pool + O_KVF);
    __nv_bfloat16* kvH  = (__nv_bfloat16*)(pool + O_KVH);
    __nv_bfloat16* kvL  = (__nv_bfloat16*)(pool + O_KVL);
    float*         opre = nx;

    cudaFuncSetAttribute(gemm_k, cudaFuncAttributeMaxDynamicSharedMemorySize, GSMEM);

    // 1. token shift (float4)
    shift_k<<<(NT*(Dd/4) + 255)/256, 256>>>((const float4*)x, (float4*)nx);
    // 2. weight transposes -> bf16 hi/lo  [out,in] K-major
    trans_split_k<<<dim3(2048/32, 512/32, 1), 256>>>(W_h,  whTH, whTL, 512, 2048);
    trans_split_k<<<dim3(128/32,  512/32, 1), 256>>>(W_qk, wqTH, wqTL, 512, 128);
    trans_split_k<<<dim3(512/32, 1024/32, 1), 256>>>(W_o,  woTH, woTL, 1024, 512);
    // 3. LN_h -> hi/lo
    ln_split_k<<<NT, 256>>>(nx, ln_h_g, ln_h_b, lnH, lnL, Dd);
    // 4. GEMM1 -> bufA (SiLU)
    gemm_k<<<dim3(16, 128, 1), 256, GSMEM>>>(lnH, lnL, whTH, whTL, bufA, nullptr, nullptr,
        NT, HIDc, Dd, b_h, 1.f, F_SILU, 0, 0, 0);
    // 5. dwconv -> hid
    dwconv4_k<<<dim3(32, 16, Bb), 256>>>((const float4*)bufA, dw_h, nullptr,
                                         (float4*)hid, HIDc);
    // 6. hid per-group transpose -> hT [bg,2048,256]
    trans_split_k<<<dim3(64, 8, 64), 256>>>(hid, hTH, hTL, 256, 2048);
    // 7. LN_qk -> hi/lo
    ln_split_k<<<NT, 256>>>(nx, ln_qk_g, ln_qk_b, lnH, lnL, Dd);
    // 8. GEMM2 -> qk (SiLU)
    gemm_k<<<dim3(1, 128, 1), 256, GSMEM>>>(lnH, lnL, wqTH, wqTL, qk, nullptr, nullptr,
        NT, DQK, Dd, b_qk, 1.f, F_SILU, 0, 0, 0);
    // 9. dwconv -> qk2
    dwconv4_k<<<dim3(2, 16, Bb), 256>>>((const float4*)qk, dw_qk, nullptr,
                                        (float4*)qk2, DQK);
    // 10. offset-scale split
    qsplit_k<<<(NT*DQK + 255)/256, 256>>>(qk2, gamma, beta, qqH, qqL, lqH, lqL, qkH, qkL, lkF);
    // 11. lin_k per-group transpose -> lkT [bg,128,256]
    trans_split_k<<<dim3(4, 8, 64), 256>>>(lkF, lkTH, lkTL, 256, 128);
    // 12. scores -> attH/attL (relu^2 causal, bf16 split)
    gemm_k<<<dim3(2, 2, 64), 256, GSMEM>>>(qqH, qqL, qkH, qkL, nullptr, attH, attL,
        GRP, GRP, DQK, nullptr, 1.f/GRP, F_SCORE,
        (long long)GRP*DQK, (long long)GRP*DQK, (long long)GRP*GRP);
    // 13. quad out: attn @ hidT^T -> bufA
    gemm_k<<<dim3(16, 2, 64), 256, GSMEM>>>(attH, attL, hTH, hTL, bufA, nullptr, nullptr,
        GRP, HIDc, GRP, nullptr, 1.f, 0,
        (long long)GRP*GRP, (long long)HIDc*GRP, (long long)GRP*HIDc);
    // 14. lin kv: lkT @ hidT^T / g -> kvF transposed [bg,2048,128]
    gemm_k<<<dim3(16, 1, 64), 256, GSMEM>>>(lkTH, lkTL, hTH, hTL, kvF, nullptr, nullptr,
        DQK, HIDc, GRP, nullptr, 1.f/GRP, F_TRC,
        (long long)DQK*GRP, (long long)HIDc*GRP, (long long)HIDc*DQK);
    // 15. exclusive group cumsum -> kvH/kvL
    cumsum_split_k<<<(int)(((size_t)Bb*2048*128 + 255)/256), 256>>>(kvF, kvH, kvL);
    // 16. lin out: lin_q @ kvT^T, accumulate into bufA
    gemm_k<<<dim3(16, 2, 64), 256, GSMEM>>>(lqH, lqL, kvH, kvL, bufA, nullptr, nullptr,
        GRP, HIDc, DQK, nullptr, 1.f, F_ACC,
        (long long)GRP*DQK, (long long)HIDc*DQK, (long long)GRP*HIDc);
    // 17. fused gating + LN_o -> lnH/lnL
    gate_ln_k<<<NT, 256>>>(bufA, hid, ln_o_g, ln_o_b, lnH, lnL);
    // 18. GEMM3 -> opre (SiLU)
    gemm_k<<<dim3(4, 128, 1), 256, GSMEM>>>(lnH, lnL, woTH, woTL, opre, nullptr, nullptr,
        NT, Dd, 2*Dd, b_o, 1.f, F_SILU, 0, 0, 0);
    // 19. dwconv + x residual -> out
    dwconv4_k<<<dim3(8, 16, Bb), 256>>>((const float4*)opre, dw_o, (const float4*)x,
                                        (float4*)out, Dd);
}

// round 6
// speedup vs baseline: 2.4509x; 1.0522x over previous
#include <cuda_runtime.h>
#include <cuda_bf16.h>
#include <cstdint>

#define Bb    8
#define Nn    2048
#define Dd    512
#define HIDc  2048
#define DQK   128
#define GRP   256
#define Gg    8
#define NT    (Bb*Nn)
#define Ee    1024
#define KK    17

// ================= warp MMA / async helpers (sm_80+ portable) =================
__device__ __forceinline__ uint32_t smem_to_u32(const void* p) {
    uint32_t a;
    asm("{ .reg .u64 t; cvta.to.shared.u64 t, %1; cvt.u32.u64 %0, t; }" : "=r"(a) : "l"(p));
    return a;
}
__device__ __forceinline__ void ldsm4(uint32_t* r, uint32_t addr) {
    asm volatile("ldmatrix.sync.aligned.m8n8.x4.shared.b16 {%0,%1,%2,%3}, [%4];"
        : "=r"(r[0]), "=r"(r[1]), "=r"(r[2]), "=r"(r[3]) : "r"(addr));
}
__device__ __forceinline__ void mma16816(float* c, const uint32_t* a, uint32_t b0, uint32_t b1) {
    asm volatile(
        "mma.sync.aligned.m16n8k16.row.col.f32.bf16.bf16.f32 "
        "{%0,%1,%2,%3}, {%4,%5,%6,%7}, {%8,%9}, {%0,%1,%2,%3};"
        : "+f"(c[0]), "+f"(c[1]), "+f"(c[2]), "+f"(c[3])
        : "r"(a[0]), "r"(a[1]), "r"(a[2]), "r"(a[3]), "r"(b0), "r"(b1));
}
__device__ __forceinline__ void cp16(uint32_t dst, const void* src) {
    asm volatile("cp.async.cg.shared.global [%0], [%1], 16;" :: "r"(dst), "l"(src));
}
#define CP_COMMIT() asm volatile("cp.async.commit_group;" ::: "memory")
#define CP_WAIT(N)  asm volatile("cp.async.wait_group %0;" :: "n"(N) : "memory")

#define F_SILU  1
#define F_ACC   2
#define F_SCORE 4
#define F_TRC   8

// ================= scratch pool =================
#define SZF(n) ((size_t)(n)*4)
#define SZB(n) ((size_t)(n)*2)
static constexpr size_t O_NX   = 0;
static constexpr size_t O_LNH  = O_NX   + SZF((size_t)NT*512);
static constexpr size_t O_LNL  = O_LNH  + SZB((size_t)NT*1024);
static constexpr size_t O_WHTH = O_LNL  + SZB((size_t)NT*1024);
static constexpr size_t O_WHTL = O_WHTH + SZB(2048*512);
static constexpr size_t O_WQTH = O_WHTL + SZB(2048*512);
static constexpr size_t O_WQTL = O_WQTH + SZB(128*512);
static constexpr size_t O_WOTH = O_WQTL + SZB(128*512);
static constexpr size_t O_WOTL = O_WOTH + SZB(512*1024);
static constexpr size_t O_BUFA = O_WOTL + SZB(512*1024);
static constexpr size_t O_HID  = O_BUFA + SZF((size_t)NT*2048);
static constexpr size_t O_HTH  = O_HID  + SZF((size_t)NT*2048);
static constexpr size_t O_HTL  = O_HTH  + SZB((size_t)NT*2048);
static constexpr size_t O_QK   = O_HTL  + SZB((size_t)NT*2048);
static constexpr size_t O_QK2  = O_QK   + SZF((size_t)NT*128);
static constexpr size_t O_QQH  = O_QK2  + SZF((size_t)NT*128);
static constexpr size_t O_QQL  = O_QQH  + SZB((size_t)NT*128);
static constexpr size_t O_LQH  = O_QQL  + SZB((size_t)NT*128);
static constexpr size_t O_LQL  = O_LQH  + SZB((size_t)NT*128);
static constexpr size_t O_QKH  = O_LQL  + SZB((size_t)NT*128);
static constexpr size_t O_QKL  = O_QKH  + SZB((size_t)NT*128);
static constexpr size_t O_LKF  = O_QKL  + SZB((size_t)NT*128);
static constexpr size_t O_LKTH = O_LKF  + SZF((size_t)NT*128);
static constexpr size_t O_LKTL = O_LKTH + SZB((size_t)NT*128);
static constexpr size_t O_ATTH = O_LKTL + SZB((size_t)NT*128);
static constexpr size_t O_ATTL = O_ATTH + SZB((size_t)64*256*256);
static constexpr size_t O_KVF  = O_ATTL + SZB((size_t)64*256*256);
static constexpr size_t O_KVH  = O_KVF  + SZF((size_t)64*2048*128);
static constexpr size_t O_KVL  = O_KVH  + SZB((size_t)64*2048*128);
static constexpr size_t O_END  = O_KVL  + SZB((size_t)64*2048*128);
__device__ __align__(1024) unsigned char g_pool[O_END];

__device__ __forceinline__ void bsplit(float v, __nv_bfloat16* h, __nv_bfloat16* l) {
    __nv_bfloat16 hv = __float2bfloat16(v);
    *h = hv;
    *l = __float2bfloat16(v - __bfloat162float(hv));
}

// ================= elementwise / prep kernels =================
__global__ void shift_k(const float4* __restrict__ x, float4* __restrict__ nx) {
    long i = (long)blockIdx.x * blockDim.x + threadIdx.x;
    if (i >= (long)NT*(Dd/4)) return;
    int c4 = (int)(i % (Dd/4));
    int n  = (int)((i / (Dd/4)) % Nn);
    if (c4 < Dd/8) nx[i] = (n == 0) ? make_float4(0,0,0,0) : x[i - Dd/4];
    else           nx[i] = x[i];
}

__global__ void ln_split_k(const float* __restrict__ in, const float* __restrict__ g,
                           const float* __restrict__ b,
                           __nv_bfloat16* __restrict__ oh, __nv_bfloat16* __restrict__ ol,
                           int C) {
    long row = blockIdx.x;
    const float* xr = in + row * C;
    float s = 0.f, s2 = 0.f;
    for (int i = threadIdx.x; i < C; i += blockDim.x) { float v = xr[i]; s += v; s2 += v*v; }
    #pragma unroll
    for (int o = 16; o; o >>= 1) {
        s  += __shfl_xor_sync(~0u, s,  o);
        s2 += __shfl_xor_sync(~0u, s2, o);
    }
    __shared__ float shs[8], shs2[8], smu, sinv;
    int w = threadIdx.x >> 5, l = threadIdx.x & 31;
    if (l == 0) { shs[w] = s; shs2[w] = s2; }
    __syncthreads();
    if (threadIdx.x == 0) {
        float ts = 0.f, ts2 = 0.f;
        for (int i = 0; i < (int)(blockDim.x >> 5); i++) { ts += shs[i]; ts2 += shs2[i]; }
        float mu = ts / C;
        smu = mu; sinv = rsqrtf(ts2 / C - mu*mu + 1e-5f);
    }
    __syncthreads();
    float mu = smu, inv = sinv;
    for (int i = threadIdx.x; i < C; i += blockDim.x) {
        float v = (xr[i] - mu) * inv * g[i] + b[i];
        bsplit(v, oh + row*C + i, ol + row*C + i);
    }
}

// fused gating + LN(1024) -> bf16 hi/lo
__global__ void gate_ln_k(const float* __restrict__ att, const float* __restrict__ hid,
                          const float* __restrict__ g, const float* __restrict__ b,
                          __nv_bfloat16* __restrict__ oh, __nv_bfloat16* __restrict__ ol) {
    long row = blockIdx.x;
    __shared__ float buf[1024];
    const float* ar = att + row*HIDc;
    const float* hr = hid + row*HIDc;
    float s = 0.f, s2 = 0.f;
    for (int i = threadIdx.x; i < 1024; i += blockDim.x) {
        float av = ar[i], au = ar[Ee + i], v = hr[i], u = hr[Ee + i];
        float val = au * v * (1.f / (1.f + expf(-(av * u))));
        buf[i] = val; s += val; s2 += val*val;
    }
    #pragma unroll
    for (int o = 16; o; o >>= 1) {
        s  += __shfl_xor_sync(~0u, s,  o);
        s2 += __shfl_xor_sync(~0u, s2, o);
    }
    __shared__ float shs[8], shs2[8], smu, sinv;
    int w = threadIdx.x >> 5, l = threadIdx.x & 31;
    if (l == 0) { shs[w] = s; shs2[w] = s2; }
    __syncthreads();
    if (threadIdx.x == 0) {
        float ts = 0.f, ts2 = 0.f;
        for (int i = 0; i < (int)(blockDim.x >> 5); i++) { ts += shs[i]; ts2 += shs2[i]; }
        float mu = ts / 1024.f;
        smu = mu; sinv = rsqrtf(ts2 / 1024.f - mu*mu + 1e-5f);
    }
    __syncthreads();
    float mu = smu, inv = sinv;
    for (int i = threadIdx.x; i < 1024; i += blockDim.x) {
        float v = (buf[i] - mu) * inv * g[i] + b[i];
        bsplit(v, oh + row*1024 + i, ol + row*1024 + i);
    }
}

__global__ void trans_split_k(const float* __restrict__ in,
                              __nv_bfloat16* __restrict__ oh, __nv_bfloat16* __restrict__ ol,
                              int R, int C) {
    __shared__ float t[32][33];
    size_t bz = (size_t)blockIdx.z * R * C;
    int c0 = blockIdx.x * 32, r0 = blockIdx.y * 32;
    int tx = threadIdx.x & 31, ty = threadIdx.x >> 5;
    #pragma unroll
    for (int i = ty; i < 32; i += 8)
        t[i][tx] = in[bz + (size_t)(r0 + i)*C + c0 + tx];
    __syncthreads();
    #pragma unroll
    for (int j = ty; j < 32; j += 8) {
        size_t o = bz + (size_t)(c0 + j)*R + r0 + tx;
        bsplit(t[tx][j], oh + o, ol + o);
    }
}

// float4-vectorized depthwise conv K=17 + residual (+ optional extra residual)
__global__ void dwconv4_k(const float4* __restrict__ h4, const float* __restrict__ dw,
                          const float4* __restrict__ extra4, float4* __restrict__ out4, int C) {
    const int CT4 = 16, NTile = 128, HALO = 8;
    __shared__ float4 sh[NTile + 2*HALO][CT4];
    __shared__ float4 sdw[KK][CT4];
    int b = blockIdx.z, n0 = blockIdx.y * NTile, c0 = blockIdx.x * CT4;
    int C4 = C >> 2;
    const float4* base = h4 + (size_t)b*Nn*C4 + c0;
    for (int idx = threadIdx.x; idx < (NTile + 2*HALO)*CT4; idx += blockDim.x) {
        int r = idx >> 4, c = idx & 15;
        int n = n0 - HALO + r;
        sh[r][c] = (n >= 0 && n < Nn) ? base[(size_t)n*C4 + c] : make_float4(0,0,0,0);
    }
    for (int idx = threadIdx.x; idx < KK*CT4; idx += blockDim.x) {
        int k = idx >> 4, c = idx & 15;
        const float* w = dw + k*C + (c0 + c)*4;
        sdw[k][c] = make_float4(w[0], w[1], w[2], w[3]);
    }
    __syncthreads();
    for (int idx = threadIdx.x; idx < NTile*CT4; idx += blockDim.x) {
        int r = idx >> 4, c = idx & 15;
        float4 acc = sh[r + HALO][c];
        #pragma unroll
        for (int k = 0; k < KK; k++) {
            float4 a = sh[r + k][c], w = sdw[k][c];
            acc.x += a.x*w.x; acc.y += a.y*w.y; acc.z += a.z*w.z; acc.w += a.w*w.w;
        }
        size_t o = (size_t)b*Nn*C4 + (size_t)(n0 + r)*C4 + c0 + c;
        if (extra4) {
            float4 e = extra4[o];
            acc.x += e.x; acc.y += e.y; acc.z += e.z; acc.w += e.w;
        }
        out4[o] = acc;
    }
}

__global__ void qsplit_k(const float* __restrict__ qk, const float* __restrict__ gamma,
                         const float* __restrict__ beta,
                         __nv_bfloat16* qqh, __nv_bfloat16* qql,
                         __nv_bfloat16* lqh, __nv_bfloat16* lql,
                         __nv_bfloat16* qkh, __nv_bfloat16* qkl,
                         float* lkf) {
    long i = (long)blockIdx.x * blockDim.x + threadIdx.x;
    if (i >= (long)NT*DQK) return;
    int d = (int)(i & 127);
    float v = qk[i];
    bsplit(v * gamma[0*DQK + d] + beta[0*DQK + d], qqh + i, qql + i);
    bsplit(v * gamma[1*DQK + d] + beta[1*DQK + d], lqh + i, lql + i);
    bsplit(v * gamma[2*DQK + d] + beta[2*DQK + d], qkh + i, qkl + i);
    lkf[i] = v * gamma[3*DQK + d] + beta[3*DQK + d];
}

__global__ void cumsum_split_k(const float* __restrict__ kvf,
                               __nv_bfloat16* __restrict__ oh,
                               __nv_bfloat16* __restrict__ ol) {
    const size_t S = (size_t)2048*128;
    long i = (long)blockIdx.x * blockDim.x + threadIdx.x;
    if (i >= (long)Bb*S) return;
    size_t b = (size_t)i / S, r = (size_t)i % S;
    size_t base = b*Gg*S + r;
    float s = 0.f;
    #pragma unroll
    for (int g = 0; g < Gg; g++) {
        size_t o = base + (size_t)g*S;
        float v = kvf[o];
        bsplit(s, oh + o, ol + o);
        s += v;
    }
}

// ================= HMMA bf16x3 GEMM — fused hi/lo staging, 128x128 tile =================
// Stage row layout (144 B): cols 0-31 = hi chunk, cols 32-63 = lo chunk (K-chunk = 32).
// Per chunk, issue all 3 combos: Ah*Bh + Al*Bh + Ah*Bl.
#define LDA 72            // bf16 elems per smem row (64 data + 8 pad) = 144 B
#define STG_BYTES 36864   // one stage: A (18432) + B (18432)
#define GSMEM (2*STG_BYTES)

__global__ void __launch_bounds__(256, 2) gemm_k(
    const __nv_bfloat16* __restrict__ Ah, const __nv_bfloat16* __restrict__ Al,
    const __nv_bfloat16* __restrict__ Bh, const __nv_bfloat16* __restrict__ Bl,
    float* C, __nv_bfloat16* Ch, __nv_bfloat16* Cl,
    int M, int N, int Ktot, const float* __restrict__ bias, float alpha, int flags,
    long long sA, long long sB, long long sC)
{
    extern __shared__ __align__(16) unsigned char smem[];
    uint32_t sbase = smem_to_u32(smem);
    int tid = threadIdx.x, lane = tid & 31, wid = tid >> 5;
    int wm = wid & 3, wn = wid >> 2;            // 4 (M) x 2 (N) warps
    int brow = blockIdx.y * 128, bcol = blockIdx.x * 128;
    long long bz = blockIdx.z;
    Ah += bz*sA; Al += bz*sA; Bh += bz*sB; Bl += bz*sB;
    if (C)  C  += bz*sC;
    if (Ch) { Ch += bz*sC; Cl += bz*sC; }

    float acc[2][8][4];
    #pragma unroll
    for (int i = 0; i < 2; i++)
        #pragma unroll
        for (int j = 0; j < 8; j++)
            #pragma unroll
            for (int q = 0; q < 4; q++) acc[i][j][q] = 0.f;

    uint32_t aOff = (uint32_t)(((wm*32 + (lane & 15)) * LDA + (lane >> 4)*8) * 2);
    uint32_t bOff = (uint32_t)(((wn*64 + ((lane >> 4) & 1)*8 + (lane & 7)) * LDA
                                + ((lane >> 3) & 1)*8) * 2) + 18432;
    const int ldr = tid >> 3, lds2 = tid & 7;   // 8 x 16B segments per 144B row
    const int seg = lds2 & 3;                   // segment within hi or lo half

    const int KC = Ktot >> 5;                   // 32-K chunks (hi+lo staged together)

    auto issue = [&](int it) {
        int k0 = it << 5;
        const __nv_bfloat16* As = (lds2 < 4) ? Ah : Al;
        const __nv_bfloat16* Bs = (lds2 < 4) ? Bh : Bl;
        uint32_t sa = sbase + (uint32_t)(it & 1)*STG_BYTES;
        #pragma unroll
        for (int e = 0; e < 4; e++) {
            int r = ldr + e*32;
            cp16(sa + (uint32_t)(r*144 + lds2*16),
                 As + (size_t)(brow + r)*Ktot + k0 + seg*8);
            cp16(sa + 18432u + (uint32_t)(r*144 + lds2*16),
                 Bs + (size_t)(bcol + r)*Ktot + k0 + seg*8);
        }
        CP_COMMIT();
    };

    issue(0);
    for (int it = 0; it < KC; ++it) {
        if (it + 1 < KC) { issue(it + 1); CP_WAIT(1); }
        else             { CP_WAIT(0); }
        __syncthreads();
        uint32_t stg = sbase + (uint32_t)(it & 1)*STG_BYTES;
        uint32_t aB = stg + aOff, bB = stg + bOff;
        #pragma unroll
        for (int kk = 0; kk < 2; kk++) {
            uint32_t afh[2][4], afl[2][4];
            #pragma unroll
            for (int i = 0; i < 2; i++) {
                ldsm4(afh[i], aB + (uint32_t)((i*16*LDA + kk*16) * 2));
                ldsm4(afl[i], aB + (uint32_t)((i*16*LDA + 32 + kk*16) * 2));
            }
            #pragma unroll
            for (int p = 0; p < 4; p++) {
                uint32_t bh[4], bl[4];
                ldsm4(bh, bB + (uint32_t)((p*16*LDA + kk*16) * 2));
                ldsm4(bl, bB + (uint32_t)((p*16*LDA + 32 + kk*16) * 2));
                #pragma unroll
                for (int i = 0; i < 2; i++) {
                    mma16816(acc[i][2*p],   afh[i], bh[0], bh[1]);
                    mma16816(acc[i][2*p+1], afh[i], bh[2], bh[3]);
                    mma16816(acc[i][2*p],   afl[i], bh[0], bh[1]);
                    mma16816(acc[i][2*p+1], afl[i], bh[2], bh[3]);
                    mma16816(acc[i][2*p],   afh[i], bl[0], bl[1]);
                    mma16816(acc[i][2*p+1], afh[i], bl[2], bl[3]);
                }
            }
        }
        __syncthreads();
    }

    // ---- epilogue ----
    int g = lane >> 2, c2 = (lane & 3)*2;
    #pragma unroll
    for (int i = 0; i < 2; i++) {
        #pragma unroll
        for (int j = 0; j < 8; j++) {
            #pragma unroll
            for (int rr = 0; rr < 2; rr++) {
                int row = brow + wm*32 + i*16 + g + rr*8;
                int col = bcol + wn*64 + j*8 + c2;
                float v0 = acc[i][j][rr*2+0] * alpha;
                float v1 = acc[i][j][rr*2+1] * alpha;
                if (flags & F_SCORE) {
                    v0 = fmaxf(v0, 0.f); v0 *= v0;
                    v1 = fmaxf(v1, 0.f); v1 *= v1;
                    if (col     > row) v0 = 0.f;
                    if (col + 1 > row) v1 = 0.f;
                    size_t o = (size_t)row*N + col;
                    __nv_bfloat16 h0 = __float2bfloat16(v0);
                    __nv_bfloat16 h1 = __float2bfloat16(v1);
                    Ch[o]   = h0; Cl[o]   = __float2bfloat16(v0 - __bfloat162float(h0));
                    Ch[o+1] = h1; Cl[o+1] = __float2bfloat16(v1 - __bfloat162float(h1));
                } else if (flags & F_TRC) {
                    C[(size_t)col*M + row]     = v0;
                    C[(size_t)(col+1)*M + row] = v1;
                } else {
                    if (bias) { v0 += bias[col]; v1 += bias[col+1]; }
                    if (flags & F_SILU) {
                        v0 = v0 / (1.f + expf(-v0));
                        v1 = v1 / (1.f + expf(-v1));
                    }
                    size_t o = (size_t)row*N + col;
                    if (flags & F_ACC) { v0 += C[o]; v1 += C[o+1]; }
                    *(float2*)(C + o) = make_float2(v0, v1);
                }
            }
        }
    }
}

// ================= launcher =================
extern "C" void kernel_launch(void* const* d_in, const int* in_sizes, int n_in,
                              void* d_out, int out_size) {
    const float* x      = (const float*)d_in[0];
    const float* ln_h_g = (const float*)d_in[1];
    const float* ln_h_b = (const float*)d_in[2];
    const float* W_h    = (const float*)d_in[3];
    const float* b_h    = (const float*)d_in[4];
    const float* dw_h   = (const float*)d_in[5];
    const float* ln_qk_g= (const float*)d_in[6];
    const float* ln_qk_b= (const float*)d_in[7];
    const float* W_qk   = (const float*)d_in[8];
    const float* b_qk   = (const float*)d_in[9];
    const float* dw_qk  = (const float*)d_in[10];
    const float* gamma  = (const float*)d_in[11];
    const float* beta   = (const float*)d_in[12];
    const float* ln_o_g = (const float*)d_in[13];
    const float* ln_o_b = (const float*)d_in[14];
    const float* W_o    = (const float*)d_in[15];
    const float* b_o    = (const float*)d_in[16];
    const float* dw_o   = (const float*)d_in[17];
    float* out = (float*)d_out;

    unsigned char* pool;
    cudaGetSymbolAddress((void**)&pool, g_pool);
    float*         nx   = (float*)(pool + O_NX);
    __nv_bfloat16* lnH  = (__nv_bfloat16*)(pool + O_LNH);
    __nv_bfloat16* lnL  = (__nv_bfloat16*)(pool + O_LNL);
    __nv_bfloat16* whTH = (__nv_bfloat16*)(pool + O_WHTH);
    __nv_bfloat16* whTL = (__nv_bfloat16*)(pool + O_WHTL);
    __nv_bfloat16* wqTH = (__nv_bfloat16*)(pool + O_WQTH);
    __nv_bfloat16* wqTL = (__nv_bfloat16*)(pool + O_WQTL);
    __nv_bfloat16* woTH = (__nv_bfloat16*)(pool + O_WOTH);
    __nv_bfloat16* woTL = (__nv_bfloat16*)(pool + O_WOTL);
    float*         bufA = (float*)(pool + O_BUFA);
    float*         hid  = (float*)(pool + O_HID);
    __nv_bfloat16* hTH  = (__nv_bfloat16*)(pool + O_HTH);
    __nv_bfloat16* hTL  = (__nv_bfloat16*)(pool + O_HTL);
    float*         qk   = (float*)(pool + O_QK);
    float*         qk2  = (float*)(pool + O_QK2);
    __nv_bfloat16* qqH  = (__nv_bfloat16*)(pool + O_QQH);
    __nv_bfloat16* qqL  = (__nv_bfloat16*)(pool + O_QQL);
    __nv_bfloat16* lqH  = (__nv_bfloat16*)(pool + O_LQH);
    __nv_bfloat16* lqL  = (__nv_bfloat16*)(pool + O_LQL);
    __nv_bfloat16* qkH  = (__nv_bfloat16*)(pool + O_QKH);
    __nv_bfloat16* qkL  = (__nv_bfloat16*)(pool + O_QKL);
    float*         lkF  = (float*)(pool + O_LKF);
    __nv_bfloat16* lkTH = (__nv_bfloat16*)(pool + O_LKTH);
    __nv_bfloat16* lkTL = (__nv_bfloat16*)(pool + O_LKTL);
    __nv_bfloat16* attH = (__nv_bfloat16*)(pool + O_ATTH);
    __nv_bfloat16* attL = (__nv_bfloat16*)(pool + O_ATTL);
    float*         kvF  = (float*)(pool + O_KVF);
    __nv_bfloat16* kvH  = (__nv_bfloat16*)(pool + O_KVH);
    __nv_bfloat16* kvL  = (__nv_bfloat16*)(pool + O_KVL);
    float*         opre = nx;

    cudaFuncSetAttribute(gemm_k, cudaFuncAttributeMaxDynamicSharedMemorySize, GSMEM);

    // 1. token shift (float4)
    shift_k<<<(NT*(Dd/4) + 255)/256, 256>>>((const float4*)x, (float4*)nx);
    // 2. weight transposes -> bf16 hi/lo  [out,in] K-major
    trans_split_k<<<dim3(2048/32, 512/32, 1), 256>>>(W_h,  whTH, whTL, 512, 2048);
    trans_split_k<<<dim3(128/32,  512/32, 1), 256>>>(W_qk, wqTH, wqTL, 512, 128);
    trans_split_k<<<dim3(512/32, 1024/32, 1), 256>>>(W_o,  woTH, woTL, 1024, 512);
    // 3. LN_h -> hi/lo
    ln_split_k<<<NT, 256>>>(nx, ln_h_g, ln_h_b, lnH, lnL, Dd);
    // 4. GEMM1 -> bufA (SiLU)
    gemm_k<<<dim3(16, 128, 1), 256, GSMEM>>>(lnH, lnL, whTH, whTL, bufA, nullptr, nullptr,
        NT, HIDc, Dd, b_h, 1.f, F_SILU, 0, 0, 0);
    // 5. dwconv -> hid
    dwconv4_k<<<dim3(32, 16, Bb), 256>>>((const float4*)bufA, dw_h, nullptr,
                                         (float4*)hid, HIDc);
    // 6. hid per-group transpose -> hT [bg,2048,256]
    trans_split_k<<<dim3(64, 8, 64), 256>>>(hid, hTH, hTL, 256, 2048);
    // 7. LN_qk -> hi/lo
    ln_split_k<<<NT, 256>>>(nx, ln_qk_g, ln_qk_b, lnH, lnL, Dd);
    // 8. GEMM2 -> qk (SiLU)
    gemm_k<<<dim3(1, 128, 1), 256, GSMEM>>>(lnH, lnL, wqTH, wqTL, qk, nullptr, nullptr,
        NT, DQK, Dd, b_qk, 1.f, F_SILU, 0, 0, 0);
    // 9. dwconv -> qk2
    dwconv4_k<<<dim3(2, 16, Bb), 256>>>((const float4*)qk, dw_qk, nullptr,
                                        (float4*)qk2, DQK);
    // 10. offset-scale split
    qsplit_k<<<(NT*DQK + 255)/256, 256>>>(qk2, gamma, beta, qqH, qqL, lqH, lqL, qkH, qkL, lkF);
    // 11. lin_k per-group transpose -> lkT [bg,128,256]
    trans_split_k<<<dim3(4, 8, 64), 256>>>(lkF, lkTH, lkTL, 256, 128);
    // 12. scores -> attH/attL (relu^2 causal, bf16 split)
    gemm_k<<<dim3(2, 2, 64), 256, GSMEM>>>(qqH, qqL, qkH, qkL, nullptr, attH, attL,
        GRP, GRP, DQK, nullptr, 1.f/GRP, F_SCORE,
        (long long)GRP*DQK, (long long)GRP*DQK, (long long)GRP*GRP);
    // 13. quad out: attn @ hidT^T -> bufA
    gemm_k<<<dim3(16, 2, 64), 256, GSMEM>>>(attH, attL, hTH, hTL, bufA, nullptr, nullptr,
        GRP, HIDc, GRP, nullptr, 1.f, 0,
        (long long)GRP*GRP, (long long)HIDc*GRP, (long long)GRP*HIDc);
    // 14. lin kv: lkT @ hidT^T / g -> kvF transposed [bg,2048,128]
    gemm_k<<<dim3(16, 1, 64), 256, GSMEM>>>(lkTH, lkTL, hTH, hTL, kvF, nullptr, nullptr,
        DQK, HIDc, GRP, nullptr, 1.f/GRP, F_TRC,
        (long long)DQK*GRP, (long long)HIDc*GRP, (long long)HIDc*DQK);
    // 15. exclusive group cumsum -> kvH/kvL
    cumsum_split_k<<<(int)(((size_t)Bb*2048*128 + 255)/256), 256>>>(kvF, kvH, kvL);
    // 16. lin out: lin_q @ kvT^T, accumulate into bufA
    gemm_k<<<dim3(16, 2, 64), 256, GSMEM>>>(lqH, lqL, kvH, kvL, bufA, nullptr, nullptr,
        GRP, HIDc, DQK, nullptr, 1.f, F_ACC,
        (long long)GRP*DQK, (long long)HIDc*DQK, (long long)GRP*HIDc);
    // 17. fused gating + LN_o -> lnH/lnL
    gate_ln_k<<<NT, 256>>>(bufA, hid, ln_o_g, ln_o_b, lnH, lnL);
    // 18. GEMM3 -> opre (SiLU)
    gemm_k<<<dim3(4, 128, 1), 256, GSMEM>>>(lnH, lnL, woTH, woTL, opre, nullptr, nullptr,
        NT, Dd, 2*Dd, b_o, 1.f, F_SILU, 0, 0, 0);
    // 19. dwconv + x residual -> out
    dwconv4_k<<<dim3(8, 16, Bb), 256>>>((const float4*)opre, dw_o, (const float4*)x,
                                        (float4*)out, Dd);
}